// round 14
// baseline (speedup 1.0000x reference)
#include <cuda_runtime.h>
#include <cuda_bf16.h>
#include <cstdint>

#define B    64
#define T    512
#define DIN  256
#define H    1024
#define G    4096   // 4*H
#define DOUT 256
#define NBLK 128
#define THR  256

typedef unsigned long long ull;
typedef unsigned char uchar;

// ---------------- recur SMEM byte layout: 3 stages x (32KB act + 16KB wt) ----------------
#define S_STAGE  49152
#define S_SG     147456              // 4 slices x 2112 floats = 33792 B
#define S_BAR    181248              // 3 mbarriers
#define SMEM_BYTES 181280

// ---------------- xproj SMEM byte layout ----------------
#define XS_A    0                    // 2 chunks x 32768
#define XS_W    65536                // 2 ngrp x (2 chunks x 16384)
#define XS_S    131072               // 2 slices x 4416 floats = 35328 B
#define XS_BAR  166400
#define XSMEM_BYTES 166432

// ---------------- device scratch ----------------
__device__ __align__(128) unsigned short g_Wf0[(size_t)NBLK * 8 * 8192];   // layer0 frag bf16 hi/lo
__device__ __align__(128) unsigned short g_Wf1[(size_t)NBLK * 16 * 8192];  // layer1
__device__ __align__(128) unsigned short g_WxF[(size_t)128 * 2 * 8192];    // xproj weights frag
__device__ __align__(128) unsigned short g_xf[(size_t)T * 32768];          // x frag: per t, 2 chunks x 32KB
__device__ float g_WlinT[(size_t)H * DOUT];       // [k][o]
__device__ float g_b0[G];
__device__ float g_b1[G];
__device__ float g_xp[(size_t)T * G * B];         // [t][n][b]
__device__ __align__(128) unsigned short g_h0f[2][131072];  // frag bf16: 8 chunks x (16KB hi + 16KB lo)
__device__ __align__(128) unsigned short g_h1f[2][131072];
__device__ float g_h1buf[(size_t)T * H * B];      // [t][u][b] fp32 for out

__device__ volatile unsigned g_bar_gen;
__device__ unsigned g_bar_cnt;

// ---------------- helpers ----------------
__device__ __forceinline__ float sigm(float x) { return 1.0f / (1.0f + __expf(-x)); }
__device__ __forceinline__ float tanh_f(float x) {
    float e = __expf(-2.0f * fabsf(x));
    float t = (1.0f - e) / (1.0f + e);
    return x >= 0.0f ? t : -t;
}
__device__ __forceinline__ void mbar_init(unsigned mbar, unsigned cnt) {
    asm volatile("mbarrier.init.shared.b64 [%0], %1;" :: "r"(mbar), "r"(cnt) : "memory");
}
__device__ __forceinline__ void mbar_expect_tx(unsigned mbar, unsigned bytes) {
    asm volatile("mbarrier.arrive.expect_tx.shared.b64 _, [%0], %1;" :: "r"(mbar), "r"(bytes) : "memory");
}
__device__ __forceinline__ void mbar_wait(unsigned mbar, unsigned phase) {
    asm volatile(
        "{\n\t"
        ".reg .pred P;\n\t"
        "WAIT_%=:\n\t"
        "mbarrier.try_wait.parity.acquire.cta.shared::cta.b64 P, [%0], %1, 0x989680;\n\t"
        "@P bra.uni DONE_%=;\n\t"
        "bra.uni WAIT_%=;\n\t"
        "DONE_%=:\n\t"
        "}"
        :: "r"(mbar), "r"(phase) : "memory");
}
__device__ __forceinline__ void bulk_cp(unsigned dst, const void* src, unsigned bytes, unsigned mbar) {
    asm volatile(
        "cp.async.bulk.shared::cluster.global.mbarrier::complete_tx::bytes [%0], [%1], %2, [%3];"
        :: "r"(dst), "l"(src), "r"(bytes), "r"(mbar) : "memory");
}
__device__ __forceinline__ void mma16816(float4& d, const uint4& a, unsigned b0, unsigned b1) {
    asm volatile("mma.sync.aligned.m16n8k16.row.col.f32.bf16.bf16.f32 "
                 "{%0,%1,%2,%3}, {%4,%5,%6,%7}, {%8,%9}, {%0,%1,%2,%3};"
                 : "+f"(d.x), "+f"(d.y), "+f"(d.z), "+f"(d.w)
                 : "r"(a.x), "r"(a.y), "r"(a.z), "r"(a.w), "r"(b0), "r"(b1));
}

// store fp32 value as A-fragment bf16 hi/lo pair
__device__ __forceinline__ void store_frag_pair(uchar* basearr, int uGlob, int b, float v) {
    int chunk = uGlob >> 7, kl = uGlob & 127;
    int kt = kl >> 4, kk = kl & 15;
    int mt = b >> 4, mm = b & 15;
    int reg = ((kk & 8) >> 2) | ((mm & 8) >> 3);
    int lane = (mm & 7) * 4 + ((kk & 7) >> 1);
    int half = kk & 1;
    int off = kt * 2048 + mt * 512 + lane * 16 + reg * 4 + half * 2;
    __nv_bfloat16 hb = __float2bfloat16_rn(v);
    float hf = __bfloat162float(hb);
    __nv_bfloat16 lb = __float2bfloat16_rn(v - hf);
    uchar* p = basearr + (size_t)chunk * 32768 + off;
    *(__nv_bfloat16*)p = hb;
    *(__nv_bfloat16*)(p + 16384) = lb;
}

// one k16-step: warp tile m32 x n32, split-bf16 (3 MMA products)
__device__ __forceinline__ void mma_kt(const uchar* actb, const uchar* wtb,
                                       int kt, int mgroup, int lane, float4 (&c)[2][4]) {
    const uchar* ab = actb + kt * 2048 + lane * 16;
    uint4 ah0 = *(const uint4*)(ab + (mgroup * 2 + 0) * 512);
    uint4 ah1 = *(const uint4*)(ab + (mgroup * 2 + 1) * 512);
    uint4 al0 = *(const uint4*)(ab + 16384 + (mgroup * 2 + 0) * 512);
    uint4 al1 = *(const uint4*)(ab + 16384 + (mgroup * 2 + 1) * 512);
    const uchar* wb = wtb + kt * 2048 + lane * 16;
    uint4 bh0 = *(const uint4*)(wb);
    uint4 bl0 = *(const uint4*)(wb + 512);
    uint4 bh1 = *(const uint4*)(wb + 1024);
    uint4 bl1 = *(const uint4*)(wb + 1536);
    mma16816(c[0][0], ah0, bh0.x, bh0.y);  mma16816(c[1][0], ah1, bh0.x, bh0.y);
    mma16816(c[0][1], ah0, bh0.z, bh0.w);  mma16816(c[1][1], ah1, bh0.z, bh0.w);
    mma16816(c[0][2], ah0, bh1.x, bh1.y);  mma16816(c[1][2], ah1, bh1.x, bh1.y);
    mma16816(c[0][3], ah0, bh1.z, bh1.w);  mma16816(c[1][3], ah1, bh1.z, bh1.w);
    mma16816(c[0][0], ah0, bl0.x, bl0.y);  mma16816(c[1][0], ah1, bl0.x, bl0.y);
    mma16816(c[0][1], ah0, bl0.z, bl0.w);  mma16816(c[1][1], ah1, bl0.z, bl0.w);
    mma16816(c[0][2], ah0, bl1.x, bl1.y);  mma16816(c[1][2], ah1, bl1.x, bl1.y);
    mma16816(c[0][3], ah0, bl1.z, bl1.w);  mma16816(c[1][3], ah1, bl1.z, bl1.w);
    mma16816(c[0][0], al0, bh0.x, bh0.y);  mma16816(c[1][0], al1, bh0.x, bh0.y);
    mma16816(c[0][1], al0, bh0.z, bh0.w);  mma16816(c[1][1], al1, bh0.z, bh0.w);
    mma16816(c[0][2], al0, bh1.x, bh1.y);  mma16816(c[1][2], al1, bh1.x, bh1.y);
    mma16816(c[0][3], al0, bh1.z, bh1.w);  mma16816(c[1][3], al1, bh1.z, bh1.w);
}

// ---------------- prep ----------------
__global__ void prep_kernel(const float* __restrict__ z, const float* __restrict__ x,
                            const float* __restrict__ Wih0, const float* __restrict__ Whh0,
                            const float* __restrict__ bih0, const float* __restrict__ bhh0,
                            const float* __restrict__ Wih1, const float* __restrict__ Whh1,
                            const float* __restrict__ bih1, const float* __restrict__ bhh1,
                            const float* __restrict__ Wlin) {
    size_t stride = (size_t)gridDim.x * blockDim.x;
    size_t tid = (size_t)blockIdx.x * blockDim.x + threadIdx.x;
    if (tid == 0) { g_bar_gen = 0; g_bar_cnt = 0; }

    // layer0 frag weights
    for (size_t e = tid; e < (size_t)NBLK * 8 * 8192; e += stride) {
        int half = e & 1;
        int slotq = (e >> 1) & 3;
        int lane = (e >> 3) & 31;
        int hl = (e >> 8) & 1;
        int nt = (e >> 9) & 1;
        int kt = (e >> 10) & 7;
        int chunk = (e >> 13) & 7;
        size_t blk = e >> 16;
        int n8sel = slotq >> 1, kHi = slotq & 1;
        int nn = lane >> 2, tig = lane & 3;
        int kk = kHi * 8 + tig * 2 + half;
        int k = chunk * 128 + kt * 16 + kk;
        int cc = nt * 16 + n8sel * 8 + nn;
        size_t n = (size_t)(cc >> 3) * H + blk * 8 + (cc & 7);
        float w = Whh0[n * H + k];
        __nv_bfloat16 hb = __float2bfloat16_rn(w);
        __nv_bfloat16 outv = hb;
        if (hl) outv = __float2bfloat16_rn(w - __bfloat162float(hb));
        g_Wf0[e] = *(unsigned short*)&outv;
    }
    // layer1 frag weights (K = 2048: first h0, then h1)
    for (size_t e = tid; e < (size_t)NBLK * 16 * 8192; e += stride) {
        int half = e & 1;
        int slotq = (e >> 1) & 3;
        int lane = (e >> 3) & 31;
        int hl = (e >> 8) & 1;
        int nt = (e >> 9) & 1;
        int kt = (e >> 10) & 7;
        int chunk = (e >> 13) & 15;
        size_t blk = e >> 17;
        int n8sel = slotq >> 1, kHi = slotq & 1;
        int nn = lane >> 2, tig = lane & 3;
        int kk = kHi * 8 + tig * 2 + half;
        int k = chunk * 128 + kt * 16 + kk;
        int cc = nt * 16 + n8sel * 8 + nn;
        size_t n = (size_t)(cc >> 3) * H + blk * 8 + (cc & 7);
        float w = (k < H) ? Wih1[n * H + k] : Whh1[n * H + (k - H)];
        __nv_bfloat16 hb = __float2bfloat16_rn(w);
        __nv_bfloat16 outv = hb;
        if (hl) outv = __float2bfloat16_rn(w - __bfloat162float(hb));
        g_Wf1[e] = *(unsigned short*)&outv;
    }
    // xproj frag weights: [nb32(128)][chunk(2)][8192]
    for (size_t e = tid; e < (size_t)128 * 2 * 8192; e += stride) {
        int half = e & 1;
        int slotq = (e >> 1) & 3;
        int lane = (e >> 3) & 31;
        int hl = (e >> 8) & 1;
        int nt = (e >> 9) & 1;
        int kt = (e >> 10) & 7;
        int chunk = (e >> 13) & 1;
        size_t nb32 = e >> 14;
        int n8sel = slotq >> 1, kHi = slotq & 1;
        int nn = lane >> 2, tig = lane & 3;
        int kk = kHi * 8 + tig * 2 + half;
        int k = chunk * 128 + kt * 16 + kk;
        size_t n = nb32 * 32 + nt * 16 + n8sel * 8 + nn;
        float w = Wih0[n * DIN + k];
        __nv_bfloat16 hb = __float2bfloat16_rn(w);
        __nv_bfloat16 outv = hb;
        if (hl) outv = __float2bfloat16_rn(w - __bfloat162float(hb));
        g_WxF[e] = *(unsigned short*)&outv;
    }
    // x frag pack: i = (b*T + tx)*256 + k  (coalesced x reads)
    for (size_t i = tid; i < (size_t)T * B * DIN; i += stride) {
        int k = i & 255;
        int tx = (i >> 8) & (T - 1);
        int b = i >> 17;
        store_frag_pair((uchar*)g_xf + (size_t)tx * 65536, k, b, x[i]);
    }
    for (size_t i = tid; i < (size_t)H * DOUT; i += stride) {
        size_t k = i / DOUT, o = i % DOUT;
        g_WlinT[i] = Wlin[o * H + k];
    }
    for (size_t i = tid; i < G; i += stride) {
        g_b0[i] = bih0[i] + bhh0[i];
        g_b1[i] = bih1[i] + bhh1[i];
    }
    for (size_t i = tid; i < H * B; i += stride) {
        int u = i >> 6, b = i & 63;
        float zv = z[(size_t)b * H + u];
        store_frag_pair((uchar*)g_h0f[0], u, b, zv);
        store_frag_pair((uchar*)g_h1f[0], u, b, zv);
    }
}

// ---------------- xproj (tensor-core): xp[t][n][b] = b0[n] + x[b][t-1] . Wih0^T ----------------
__global__ void __launch_bounds__(256, 1) xproj_kernel() {
    extern __shared__ uchar xs[];
    int t = blockIdx.y;
    int nb = blockIdx.x;             // 64-col group
    int tid = threadIdx.x;

    if (t == 0) {   // zero input step: bias only
        int n_local = tid >> 2, bb = (tid & 3) * 16;
        float bv = g_b0[nb * 64 + n_local];
        float4 v = make_float4(bv, bv, bv, bv);
        float4* dst = (float4*)&g_xp[(size_t)(nb * 64 + n_local) * B + bb];
        dst[0] = v; dst[1] = v; dst[2] = v; dst[3] = v;
        return;
    }

    unsigned sb = (unsigned)__cvta_generic_to_shared(xs);
    unsigned bar = sb + XS_BAR;
    if (tid == 0) {
        mbar_init(bar, 1);
        asm volatile("fence.proxy.async.shared::cta;" ::: "memory");
    }
    __syncthreads();
    if (tid == 0) {
        mbar_expect_tx(bar, 131072u);
        bulk_cp(sb + XS_A, (const uchar*)g_xf + (size_t)(t - 1) * 65536, 65536u, bar);
        bulk_cp(sb + XS_W, (const uchar*)g_WxF + (size_t)nb * 65536, 65536u, bar);
    }
    mbar_wait(bar, 0);

    int wid = tid >> 5, lane = tid & 31;
    int ksx = wid & 1, ngrp = (wid >> 1) & 1, mgrp = wid >> 2;
    float4 cacc[2][4];
#pragma unroll
    for (int i = 0; i < 2; i++)
#pragma unroll
        for (int j = 0; j < 4; j++) cacc[i][j] = make_float4(0.f, 0.f, 0.f, 0.f);

    const uchar* actb = xs + XS_A + ksx * 32768;
    const uchar* wtb  = xs + XS_W + ngrp * 32768 + ksx * 16384;
#pragma unroll
    for (int kt = 0; kt < 8; kt++)
        mma_kt(actb, wtb, kt, mgrp, lane, cacc);

    // stage [b][n] per k-slice, stride 69
    float* sgx = (float*)(xs + XS_S) + ksx * 4416;
#pragma unroll
    for (int mt = 0; mt < 2; mt++)
#pragma unroll
        for (int j = 0; j < 4; j++) {
            float4 v = cacc[mt][j];
            int row0 = mgrp * 32 + mt * 16 + (lane >> 2);
            int col = ngrp * 32 + j * 8 + (lane & 3) * 2;
            sgx[row0 * 69 + col] = v.x;
            sgx[row0 * 69 + col + 1] = v.y;
            sgx[(row0 + 8) * 69 + col] = v.z;
            sgx[(row0 + 8) * 69 + col + 1] = v.w;
        }
    __syncthreads();

    const float* sg0 = (const float*)(xs + XS_S);
    const float* sg1 = sg0 + 4416;
    int n_local = tid >> 2, bb = (tid & 3) * 16;
    float bv = g_b0[nb * 64 + n_local];
    float* dst = &g_xp[((size_t)t * G + nb * 64 + n_local) * B + bb];
#pragma unroll
    for (int q = 0; q < 4; q++) {
        float4 v;
        v.x = sg0[(bb + q * 4 + 0) * 69 + n_local] + sg1[(bb + q * 4 + 0) * 69 + n_local] + bv;
        v.y = sg0[(bb + q * 4 + 1) * 69 + n_local] + sg1[(bb + q * 4 + 1) * 69 + n_local] + bv;
        v.z = sg0[(bb + q * 4 + 2) * 69 + n_local] + sg1[(bb + q * 4 + 2) * 69 + n_local] + bv;
        v.w = sg0[(bb + q * 4 + 3) * 69 + n_local] + sg1[(bb + q * 4 + 3) * 69 + n_local] + bv;
        ((float4*)dst)[q] = v;
    }
}

// ---------------- persistent recurrent kernel ----------------
__device__ __forceinline__ void grid_sync(unsigned target) {
    __syncthreads();
    if (threadIdx.x == 0) {
        __threadfence();
        if (atomicAdd(&g_bar_cnt, 1u) == NBLK - 1) {
            g_bar_cnt = 0;
            __threadfence();
            g_bar_gen = target;
        } else {
            while (g_bar_gen < target) {}
            __threadfence();
        }
    }
    __syncthreads();
}

__device__ __forceinline__ void issue_stage(unsigned sb, int stage,
                                            const uchar* act, const uchar* wt) {
    unsigned bar = sb + S_BAR + stage * 8;
    mbar_expect_tx(bar, 49152u);
    bulk_cp(sb + stage * S_STAGE, act, 32768u, bar);
    bulk_cp(sb + stage * S_STAGE + 32768, wt, 16384u, bar);
}

__device__ __forceinline__ void chunk_src(int i, const uchar* h0src, const uchar* h1src,
                                          const uchar* wf0base, const uchar* wf1base,
                                          const uchar*& act, const uchar*& wt) {
    if (i < 16) {   // layer1 chunk
        act = (i < 8) ? h0src + (size_t)i * 32768 : h1src + (size_t)(i - 8) * 32768;
        wt = wf1base + (size_t)i * 16384;
    } else {        // layer0 (next step) chunk
        act = h0src + (size_t)(i - 16) * 32768;
        wt = wf0base + (size_t)(i - 16) * 16384;
    }
}

__global__ void __launch_bounds__(THR, 1) recur_kernel() {
    extern __shared__ uchar smem[];
    unsigned sb = (unsigned)__cvta_generic_to_shared(smem);
    float* sg4 = (float*)(smem + S_SG);

    int tid = threadIdx.x;
    int blk = blockIdx.x;
    int wrp = tid >> 5, lane = tid & 31;
    int ks = wrp & 3;          // K-split slice: handles kt = ks, ks+4
    int mgroup = wrp >> 2;     // batches mgroup*32 .. +31
    int u0 = blk * 8;

    // gate-phase ownership: 2 (unit,batch) items per thread
    int u_[2], b_[2];
    float b1v[2][4];
#pragma unroll
    for (int j = 0; j < 2; j++) {
        int item = tid + j * THR;
        u_[j] = item >> 6;
        b_[j] = item & 63;
#pragma unroll
        for (int g = 0; g < 4; g++)
            b1v[j][g] = g_b1[g * H + u0 + u_[j]];
    }

    if (tid == 0) {
        mbar_init(sb + S_BAR, 1);
        mbar_init(sb + S_BAR + 8, 1);
        mbar_init(sb + S_BAR + 16, 1);
        asm volatile("fence.proxy.async.shared::cta;" ::: "memory");
    }
    __syncthreads();

    unsigned ph_bits = 0;      // per-stage phase parity
    float c0r[2] = {0.0f, 0.0f};
    float c1r[2] = {0.0f, 0.0f};

    const uchar* wf0base = (const uchar*)&g_Wf0[(size_t)blk * 8 * 8192];
    const uchar* wf1base = (const uchar*)&g_Wf1[(size_t)blk * 16 * 8192];

    float4 acc0[2][4], acc1[2][4];

    // ================= prologue: L0(0) =================
    {
        const uchar* h00 = (const uchar*)g_h0f[0];
        if (tid == 0) {
            issue_stage(sb, 0, h00, wf0base);
            issue_stage(sb, 1, h00 + 32768, wf0base + 16384);
        }
#pragma unroll
        for (int i = 0; i < 2; i++)
#pragma unroll
            for (int j = 0; j < 4; j++) acc0[i][j] = make_float4(0.f, 0.f, 0.f, 0.f);
        for (int i = 0; i < 8; i++) {
            int stage = i % 3;
            if (tid == 0 && i + 2 < 8)
                issue_stage(sb, (i + 2) % 3, h00 + (size_t)(i + 2) * 32768,
                            wf0base + (size_t)(i + 2) * 16384);
            mbar_wait(sb + S_BAR + stage * 8, (ph_bits >> stage) & 1);
            ph_bits ^= 1u << stage;
            const uchar* actb = smem + stage * S_STAGE;
            const uchar* wtb = actb + 32768;
            mma_kt(actb, wtb, ks, mgroup, lane, acc0);
            mma_kt(actb, wtb, ks + 4, mgroup, lane, acc0);
            __syncthreads();
        }
        // L0(0) gates -> h0f[1]
        float* sgS = sg4 + ks * 2112;
#pragma unroll
        for (int mt = 0; mt < 2; mt++)
#pragma unroll
            for (int j = 0; j < 4; j++) {
                float4 v = acc0[mt][j];
                int row0 = mgroup * 32 + mt * 16 + (lane >> 2);
                int colb = j * 8 + (lane & 3) * 2;
                sgS[row0 * 33 + colb] = v.x;
                sgS[row0 * 33 + colb + 1] = v.y;
                sgS[(row0 + 8) * 33 + colb] = v.z;
                sgS[(row0 + 8) * 33 + colb + 1] = v.w;
            }
        __syncthreads();
#pragma unroll
        for (int j = 0; j < 2; j++) {
            int u = u_[j], b = b_[j];
            float gv[4];
#pragma unroll
            for (int g = 0; g < 4; g++) {
                float s = g_xp[((size_t)0 * G + g * H + u0 + u) * B + b];
#pragma unroll
                for (int sI = 0; sI < 4; sI++)
                    s += sg4[sI * 2112 + b * 33 + g * 8 + u];
                gv[g] = s;
            }
            float cc = sigm(gv[1]) * c0r[j] + sigm(gv[0]) * tanh_f(gv[2]);
            c0r[j] = cc;
            float h = sigm(gv[3]) * tanh_f(cc);
            store_frag_pair((uchar*)g_h0f[1], u0 + u, b, h);
        }
    }

    // ================= main loop: one grid sync per step =================
    for (int t = 0; t < T; t++) {
        grid_sync(t + 1);
        const uchar* h0src = (const uchar*)g_h0f[(t + 1) & 1];  // h0(t), input to L1(t) and L0(t+1)
        const uchar* h1src = (const uchar*)g_h1f[t & 1];        // h1(t-1)
        int NCH = (t == T - 1) ? 16 : 24;

        if (tid == 0) {
            const uchar *a0, *w0, *a1, *w1;
            chunk_src(0, h0src, h1src, wf0base, wf1base, a0, w0);
            chunk_src(1, h0src, h1src, wf0base, wf1base, a1, w1);
            issue_stage(sb, 0, a0, w0);
            issue_stage(sb, 1, a1, w1);
        }
#pragma unroll
        for (int i = 0; i < 2; i++)
#pragma unroll
            for (int j = 0; j < 4; j++) {
                acc1[i][j] = make_float4(0.f, 0.f, 0.f, 0.f);
                acc0[i][j] = make_float4(0.f, 0.f, 0.f, 0.f);
            }

        for (int i = 0; i < NCH; i++) {
            int stage = i % 3;
            if (tid == 0 && i + 2 < NCH) {
                const uchar *an, *wn;
                chunk_src(i + 2, h0src, h1src, wf0base, wf1base, an, wn);
                issue_stage(sb, (i + 2) % 3, an, wn);
            }
            mbar_wait(sb + S_BAR + stage * 8, (ph_bits >> stage) & 1);
            ph_bits ^= 1u << stage;
            const uchar* actb = smem + stage * S_STAGE;
            const uchar* wtb = actb + 32768;
            if (i < 16) {
                mma_kt(actb, wtb, ks, mgroup, lane, acc1);
                mma_kt(actb, wtb, ks + 4, mgroup, lane, acc1);
            } else {
                mma_kt(actb, wtb, ks, mgroup, lane, acc0);
                mma_kt(actb, wtb, ks + 4, mgroup, lane, acc0);
            }
            __syncthreads();

            if (i == 15) {
                // ---- L1(t) gates interleaved: TMA for L0 chunks continues in background ----
                {
                    float* sgS = sg4 + ks * 2112;
#pragma unroll
                    for (int mt = 0; mt < 2; mt++)
#pragma unroll
                        for (int j = 0; j < 4; j++) {
                            float4 v = acc1[mt][j];
                            int row0 = mgroup * 32 + mt * 16 + (lane >> 2);
                            int colb = j * 8 + (lane & 3) * 2;
                            sgS[row0 * 33 + colb] = v.x;
                            sgS[row0 * 33 + colb + 1] = v.y;
                            sgS[(row0 + 8) * 33 + colb] = v.z;
                            sgS[(row0 + 8) * 33 + colb + 1] = v.w;
                        }
                }
                __syncthreads();
#pragma unroll
                for (int j = 0; j < 2; j++) {
                    int u = u_[j], b = b_[j];
                    float gv[4];
#pragma unroll
                    for (int g = 0; g < 4; g++) {
                        float s = b1v[j][g];
#pragma unroll
                        for (int sI = 0; sI < 4; sI++)
                            s += sg4[sI * 2112 + b * 33 + g * 8 + u];
                        gv[g] = s;
                    }
                    float cc = sigm(gv[1]) * c1r[j] + sigm(gv[0]) * tanh_f(gv[2]);
                    c1r[j] = cc;
                    float h = sigm(gv[3]) * tanh_f(cc);
                    store_frag_pair((uchar*)g_h1f[(t + 1) & 1], u0 + u, b, h);
                    g_h1buf[(size_t)t * H * B + (u0 + u) * B + b] = h;
                }
                __syncthreads();   // protect sg4 before L0 gate staging reuses it
            }
        }

        // ---- L0(t+1) gates -> h0f[t&1] ----
        if (t + 1 < T) {
            {
                float* sgS = sg4 + ks * 2112;
#pragma unroll
                for (int mt = 0; mt < 2; mt++)
#pragma unroll
                    for (int j = 0; j < 4; j++) {
                        float4 v = acc0[mt][j];
                        int row0 = mgroup * 32 + mt * 16 + (lane >> 2);
                        int colb = j * 8 + (lane & 3) * 2;
                        sgS[row0 * 33 + colb] = v.x;
                        sgS[row0 * 33 + colb + 1] = v.y;
                        sgS[(row0 + 8) * 33 + colb] = v.z;
                        sgS[(row0 + 8) * 33 + colb + 1] = v.w;
                    }
            }
            __syncthreads();
#pragma unroll
            for (int j = 0; j < 2; j++) {
                int u = u_[j], b = b_[j];
                float gv[4];
#pragma unroll
                for (int g = 0; g < 4; g++) {
                    float s = g_xp[((size_t)(t + 1) * G + g * H + u0 + u) * B + b];
#pragma unroll
                    for (int sI = 0; sI < 4; sI++)
                        s += sg4[sI * 2112 + b * 33 + g * 8 + u];
                    gv[g] = s;
                }
                float cc = sigm(gv[1]) * c0r[j] + sigm(gv[0]) * tanh_f(gv[2]);
                c0r[j] = cc;
                float h = sigm(gv[3]) * tanh_f(cc);
                store_frag_pair((uchar*)g_h0f[t & 1], u0 + u, b, h);
            }
        }
    }
}

// ---------------- out: out[b][t][o] = blin[o] + sum_k h1buf[t][k][b] * WlinT[k][o] ----------------
__global__ __launch_bounds__(256) void out_kernel(const float* __restrict__ blin,
                                                  float* __restrict__ out) {
    int t = blockIdx.y;
    int o0 = blockIdx.x * 64;
    int tid = threadIdx.x;
    int w = tid >> 5, l = tid & 31;

    __shared__ float sh[64 * 64];   // [k][b]
    float acc0[8], acc1[8];
#pragma unroll
    for (int i = 0; i < 8; i++) { acc0[i] = 0.0f; acc1[i] = 0.0f; }

    for (int k0 = 0; k0 < H; k0 += 64) {
        __syncthreads();
#pragma unroll
        for (int r = 0; r < 4; r++) {
            int idx = tid + r * 256;
            ((float4*)sh)[idx] =
                *(((const float4*)&g_h1buf[((size_t)t * H + k0) * B]) + idx);
        }
        __syncthreads();
#pragma unroll 8
        for (int kk = 0; kk < 64; kk++) {
            const float* wr = &g_WlinT[(size_t)(k0 + kk) * DOUT + o0];
            float wa = wr[l];
            float wb = wr[32 + l];
#pragma unroll
            for (int i = 0; i < 8; i++) {
                float av = sh[kk * 64 + w * 8 + i];
                acc0[i] += wa * av;
                acc1[i] += wb * av;
            }
        }
    }
    float ba = blin[o0 + l], bb = blin[o0 + 32 + l];
#pragma unroll
    for (int i = 0; i < 8; i++) {
        int b = w * 8 + i;
        size_t base = ((size_t)b * T + t) * DOUT + o0;
        out[base + l] = acc0[i] + ba;
        out[base + 32 + l] = acc1[i] + bb;
    }
}

// ---------------- launch ----------------
extern "C" void kernel_launch(void* const* d_in, const int* in_sizes, int n_in,
                              void* d_out, int out_size) {
    const float* z    = (const float*)d_in[0];
    const float* x    = (const float*)d_in[1];
    const float* Wih0 = (const float*)d_in[2];
    const float* Whh0 = (const float*)d_in[3];
    const float* bih0 = (const float*)d_in[4];
    const float* bhh0 = (const float*)d_in[5];
    const float* Wih1 = (const float*)d_in[6];
    const float* Whh1 = (const float*)d_in[7];
    const float* bih1 = (const float*)d_in[8];
    const float* bhh1 = (const float*)d_in[9];
    const float* Wlin = (const float*)d_in[10];
    const float* blin = (const float*)d_in[11];
    float* out = (float*)d_out;

    cudaFuncSetAttribute(recur_kernel, cudaFuncAttributeMaxDynamicSharedMemorySize,
                         SMEM_BYTES);
    cudaFuncSetAttribute(xproj_kernel, cudaFuncAttributeMaxDynamicSharedMemorySize,
                         XSMEM_BYTES);

    prep_kernel<<<512, 256>>>(z, x, Wih0, Whh0, bih0, bhh0, Wih1, Whh1, bih1, bhh1, Wlin);
    xproj_kernel<<<dim3(G / 64, T), 256, XSMEM_BYTES>>>();
    recur_kernel<<<NBLK, THR, SMEM_BYTES>>>();
    out_kernel<<<dim3(DOUT / 64, T), 256>>>(blin, out);
}

// round 15
// speedup vs baseline: 1.7703x; 1.7703x over previous
#include <cuda_runtime.h>
#include <cuda_bf16.h>
#include <cuda_fp16.h>
#include <cstdint>

#define B    64
#define T    512
#define DIN  256
#define H    1024
#define G    4096   // 4*H
#define DOUT 256
#define NBLK 128
#define THR  256

typedef unsigned long long ull;
typedef unsigned char uchar;

// ---------------- recur SMEM byte layout: 3 stages x (16KB act + 16KB wt) ----------------
#define S_STAGE  32768
#define S_SG     98304               // 4 slices x 2112 floats = 33792 B
#define S_BAR    132096              // 3 mbarriers
#define SMEM_BYTES 132128

// ---------------- xproj SMEM byte layout (unchanged, bf16 path) ----------------
#define XS_A    0                    // 2 chunks x 32768
#define XS_W    65536                // 2 ngrp x (2 chunks x 16384)
#define XS_S    131072               // 2 slices x 4416 floats = 35328 B
#define XS_BAR  166400
#define XSMEM_BYTES 166432

// ---------------- device scratch ----------------
__device__ __align__(128) unsigned short g_Wf0[(size_t)NBLK * 8 * 8192];   // layer0 fp16 wh/wl frag
__device__ __align__(128) unsigned short g_Wf1[(size_t)NBLK * 16 * 8192];  // layer1
__device__ __align__(128) unsigned short g_WxF[(size_t)128 * 2 * 8192];    // xproj weights frag (bf16)
__device__ __align__(128) unsigned short g_xf[(size_t)T * 32768];          // x frag (bf16 hi/lo)
__device__ float g_WlinT[(size_t)H * DOUT];       // [k][o]
__device__ float g_b0[G];
__device__ float g_b1[G];
__device__ float g_xp[(size_t)T * G * B];         // [t][n][b]
__device__ __align__(128) unsigned short g_h0f[2][65536];   // fp16 acts: 8 chunks x 16KB
__device__ __align__(128) unsigned short g_h1f[2][65536];
__device__ float g_h1buf[(size_t)T * H * B];      // [t][u][b] fp32 for out

__device__ volatile unsigned g_bar_gen;
__device__ unsigned g_bar_cnt;

// ---------------- helpers ----------------
__device__ __forceinline__ float sigm(float x) { return 1.0f / (1.0f + __expf(-x)); }
__device__ __forceinline__ float tanh_f(float x) {
    float e = __expf(-2.0f * fabsf(x));
    float t = (1.0f - e) / (1.0f + e);
    return x >= 0.0f ? t : -t;
}
__device__ __forceinline__ void mbar_init(unsigned mbar, unsigned cnt) {
    asm volatile("mbarrier.init.shared.b64 [%0], %1;" :: "r"(mbar), "r"(cnt) : "memory");
}
__device__ __forceinline__ void mbar_expect_tx(unsigned mbar, unsigned bytes) {
    asm volatile("mbarrier.arrive.expect_tx.shared.b64 _, [%0], %1;" :: "r"(mbar), "r"(bytes) : "memory");
}
__device__ __forceinline__ void mbar_wait(unsigned mbar, unsigned phase) {
    asm volatile(
        "{\n\t"
        ".reg .pred P;\n\t"
        "WAIT_%=:\n\t"
        "mbarrier.try_wait.parity.acquire.cta.shared::cta.b64 P, [%0], %1, 0x989680;\n\t"
        "@P bra.uni DONE_%=;\n\t"
        "bra.uni WAIT_%=;\n\t"
        "DONE_%=:\n\t"
        "}"
        :: "r"(mbar), "r"(phase) : "memory");
}
__device__ __forceinline__ void bulk_cp(unsigned dst, const void* src, unsigned bytes, unsigned mbar) {
    asm volatile(
        "cp.async.bulk.shared::cluster.global.mbarrier::complete_tx::bytes [%0], [%1], %2, [%3];"
        :: "r"(dst), "l"(src), "r"(bytes), "r"(mbar) : "memory");
}
// bf16 mma (xproj path)
__device__ __forceinline__ void mma16816(float4& d, const uint4& a, unsigned b0, unsigned b1) {
    asm volatile("mma.sync.aligned.m16n8k16.row.col.f32.bf16.bf16.f32 "
                 "{%0,%1,%2,%3}, {%4,%5,%6,%7}, {%8,%9}, {%0,%1,%2,%3};"
                 : "+f"(d.x), "+f"(d.y), "+f"(d.z), "+f"(d.w)
                 : "r"(a.x), "r"(a.y), "r"(a.z), "r"(a.w), "r"(b0), "r"(b1));
}
// fp16 mma (recur path)
__device__ __forceinline__ void hmma16816(float4& d, const uint4& a, unsigned b0, unsigned b1) {
    asm volatile("mma.sync.aligned.m16n8k16.row.col.f32.f16.f16.f32 "
                 "{%0,%1,%2,%3}, {%4,%5,%6,%7}, {%8,%9}, {%0,%1,%2,%3};"
                 : "+f"(d.x), "+f"(d.y), "+f"(d.z), "+f"(d.w)
                 : "r"(a.x), "r"(a.y), "r"(a.z), "r"(a.w), "r"(b0), "r"(b1));
}

// ---- bf16 hi/lo frag store (xproj x packing only; 32KB chunks) ----
__device__ __forceinline__ void store_frag_pair(uchar* basearr, int uGlob, int b, float v) {
    int chunk = uGlob >> 7, kl = uGlob & 127;
    int kt = kl >> 4, kk = kl & 15;
    int mt = b >> 4, mm = b & 15;
    int reg = ((kk & 8) >> 2) | ((mm & 8) >> 3);
    int lane = (mm & 7) * 4 + ((kk & 7) >> 1);
    int half = kk & 1;
    int off = kt * 2048 + mt * 512 + lane * 16 + reg * 4 + half * 2;
    __nv_bfloat16 hb = __float2bfloat16_rn(v);
    float hf = __bfloat162float(hb);
    __nv_bfloat16 lb = __float2bfloat16_rn(v - hf);
    uchar* p = basearr + (size_t)chunk * 32768 + off;
    *(__nv_bfloat16*)p = hb;
    *(__nv_bfloat16*)(p + 16384) = lb;
}
// ---- fp16 single-plane frag store (recur acts; 16KB chunks) ----
__device__ __forceinline__ void store_frag_h(uchar* basearr, int uGlob, int b, float v) {
    int chunk = uGlob >> 7, kl = uGlob & 127;
    int kt = kl >> 4, kk = kl & 15;
    int mt = b >> 4, mm = b & 15;
    int reg = ((kk & 8) >> 2) | ((mm & 8) >> 3);
    int lane = (mm & 7) * 4 + ((kk & 7) >> 1);
    int half = kk & 1;
    int off = kt * 2048 + mt * 512 + lane * 16 + reg * 4 + half * 2;
    *(__half*)(basearr + (size_t)chunk * 16384 + off) = __float2half_rn(v);
}

// bf16 3-term k16-step (xproj path; act chunk 32KB hi/lo)
__device__ __forceinline__ void mma_kt(const uchar* actb, const uchar* wtb,
                                       int kt, int mgroup, int lane, float4 (&c)[2][4]) {
    const uchar* ab = actb + kt * 2048 + lane * 16;
    uint4 ah0 = *(const uint4*)(ab + (mgroup * 2 + 0) * 512);
    uint4 ah1 = *(const uint4*)(ab + (mgroup * 2 + 1) * 512);
    uint4 al0 = *(const uint4*)(ab + 16384 + (mgroup * 2 + 0) * 512);
    uint4 al1 = *(const uint4*)(ab + 16384 + (mgroup * 2 + 1) * 512);
    const uchar* wb = wtb + kt * 2048 + lane * 16;
    uint4 bh0 = *(const uint4*)(wb);
    uint4 bl0 = *(const uint4*)(wb + 512);
    uint4 bh1 = *(const uint4*)(wb + 1024);
    uint4 bl1 = *(const uint4*)(wb + 1536);
    mma16816(c[0][0], ah0, bh0.x, bh0.y);  mma16816(c[1][0], ah1, bh0.x, bh0.y);
    mma16816(c[0][1], ah0, bh0.z, bh0.w);  mma16816(c[1][1], ah1, bh0.z, bh0.w);
    mma16816(c[0][2], ah0, bh1.x, bh1.y);  mma16816(c[1][2], ah1, bh1.x, bh1.y);
    mma16816(c[0][3], ah0, bh1.z, bh1.w);  mma16816(c[1][3], ah1, bh1.z, bh1.w);
    mma16816(c[0][0], ah0, bl0.x, bl0.y);  mma16816(c[1][0], ah1, bl0.x, bl0.y);
    mma16816(c[0][1], ah0, bl0.z, bl0.w);  mma16816(c[1][1], ah1, bl0.z, bl0.w);
    mma16816(c[0][2], ah0, bl1.x, bl1.y);  mma16816(c[1][2], ah1, bl1.x, bl1.y);
    mma16816(c[0][3], ah0, bl1.z, bl1.w);  mma16816(c[1][3], ah1, bl1.z, bl1.w);
    mma16816(c[0][0], al0, bh0.x, bh0.y);  mma16816(c[1][0], al1, bh0.x, bh0.y);
    mma16816(c[0][1], al0, bh0.z, bh0.w);  mma16816(c[1][1], al1, bh0.z, bh0.w);
    mma16816(c[0][2], al0, bh1.x, bh1.y);  mma16816(c[1][2], al1, bh1.x, bh1.y);
    mma16816(c[0][3], al0, bh1.z, bh1.w);  mma16816(c[1][3], al1, bh1.z, bh1.w);
}

// fp16 2-term k16-step (recur path; act chunk 16KB single plane)
__device__ __forceinline__ void mma_kt_h(const uchar* actb, const uchar* wtb,
                                         int kt, int mgroup, int lane, float4 (&c)[2][4]) {
    const uchar* ab = actb + kt * 2048 + lane * 16;
    uint4 a0 = *(const uint4*)(ab + (mgroup * 2 + 0) * 512);
    uint4 a1 = *(const uint4*)(ab + (mgroup * 2 + 1) * 512);
    const uchar* wb = wtb + kt * 2048 + lane * 16;
    uint4 bh0 = *(const uint4*)(wb);
    uint4 bl0 = *(const uint4*)(wb + 512);
    uint4 bh1 = *(const uint4*)(wb + 1024);
    uint4 bl1 = *(const uint4*)(wb + 1536);
    hmma16816(c[0][0], a0, bh0.x, bh0.y);  hmma16816(c[1][0], a1, bh0.x, bh0.y);
    hmma16816(c[0][1], a0, bh0.z, bh0.w);  hmma16816(c[1][1], a1, bh0.z, bh0.w);
    hmma16816(c[0][2], a0, bh1.x, bh1.y);  hmma16816(c[1][2], a1, bh1.x, bh1.y);
    hmma16816(c[0][3], a0, bh1.z, bh1.w);  hmma16816(c[1][3], a1, bh1.z, bh1.w);
    hmma16816(c[0][0], a0, bl0.x, bl0.y);  hmma16816(c[1][0], a1, bl0.x, bl0.y);
    hmma16816(c[0][1], a0, bl0.z, bl0.w);  hmma16816(c[1][1], a1, bl0.z, bl0.w);
    hmma16816(c[0][2], a0, bl1.x, bl1.y);  hmma16816(c[1][2], a1, bl1.x, bl1.y);
    hmma16816(c[0][3], a0, bl1.z, bl1.w);  hmma16816(c[1][3], a1, bl1.z, bl1.w);
}

// ---------------- prep ----------------
__global__ void prep_kernel(const float* __restrict__ z, const float* __restrict__ x,
                            const float* __restrict__ Wih0, const float* __restrict__ Whh0,
                            const float* __restrict__ bih0, const float* __restrict__ bhh0,
                            const float* __restrict__ Wih1, const float* __restrict__ Whh1,
                            const float* __restrict__ bih1, const float* __restrict__ bhh1,
                            const float* __restrict__ Wlin) {
    size_t stride = (size_t)gridDim.x * blockDim.x;
    size_t tid = (size_t)blockIdx.x * blockDim.x + threadIdx.x;
    if (tid == 0) { g_bar_gen = 0; g_bar_cnt = 0; }

    // layer0 frag weights (fp16 wh/wl)
    for (size_t e = tid; e < (size_t)NBLK * 8 * 8192; e += stride) {
        int half = e & 1;
        int slotq = (e >> 1) & 3;
        int lane = (e >> 3) & 31;
        int hl = (e >> 8) & 1;
        int nt = (e >> 9) & 1;
        int kt = (e >> 10) & 7;
        int chunk = (e >> 13) & 7;
        size_t blk = e >> 16;
        int n8sel = slotq >> 1, kHi = slotq & 1;
        int nn = lane >> 2, tig = lane & 3;
        int kk = kHi * 8 + tig * 2 + half;
        int k = chunk * 128 + kt * 16 + kk;
        int cc = nt * 16 + n8sel * 8 + nn;
        size_t n = (size_t)(cc >> 3) * H + blk * 8 + (cc & 7);
        float w = Whh0[n * H + k];
        __half hh = __float2half_rn(w);
        __half outv = hl ? __float2half_rn(w - __half2float(hh)) : hh;
        g_Wf0[e] = *(unsigned short*)&outv;
    }
    // layer1 frag weights (K = 2048: first h0, then h1)
    for (size_t e = tid; e < (size_t)NBLK * 16 * 8192; e += stride) {
        int half = e & 1;
        int slotq = (e >> 1) & 3;
        int lane = (e >> 3) & 31;
        int hl = (e >> 8) & 1;
        int nt = (e >> 9) & 1;
        int kt = (e >> 10) & 7;
        int chunk = (e >> 13) & 15;
        size_t blk = e >> 17;
        int n8sel = slotq >> 1, kHi = slotq & 1;
        int nn = lane >> 2, tig = lane & 3;
        int kk = kHi * 8 + tig * 2 + half;
        int k = chunk * 128 + kt * 16 + kk;
        int cc = nt * 16 + n8sel * 8 + nn;
        size_t n = (size_t)(cc >> 3) * H + blk * 8 + (cc & 7);
        float w = (k < H) ? Wih1[n * H + k] : Whh1[n * H + (k - H)];
        __half hh = __float2half_rn(w);
        __half outv = hl ? __float2half_rn(w - __half2float(hh)) : hh;
        g_Wf1[e] = *(unsigned short*)&outv;
    }
    // xproj frag weights (bf16, unchanged)
    for (size_t e = tid; e < (size_t)128 * 2 * 8192; e += stride) {
        int half = e & 1;
        int slotq = (e >> 1) & 3;
        int lane = (e >> 3) & 31;
        int hl = (e >> 8) & 1;
        int nt = (e >> 9) & 1;
        int kt = (e >> 10) & 7;
        int chunk = (e >> 13) & 1;
        size_t nb32 = e >> 14;
        int n8sel = slotq >> 1, kHi = slotq & 1;
        int nn = lane >> 2, tig = lane & 3;
        int kk = kHi * 8 + tig * 2 + half;
        int k = chunk * 128 + kt * 16 + kk;
        size_t n = nb32 * 32 + nt * 16 + n8sel * 8 + nn;
        float w = Wih0[n * DIN + k];
        __nv_bfloat16 hb = __float2bfloat16_rn(w);
        __nv_bfloat16 outv = hb;
        if (hl) outv = __float2bfloat16_rn(w - __bfloat162float(hb));
        g_WxF[e] = *(unsigned short*)&outv;
    }
    // x frag pack (bf16, unchanged)
    for (size_t i = tid; i < (size_t)T * B * DIN; i += stride) {
        int k = i & 255;
        int tx = (i >> 8) & (T - 1);
        int b = i >> 17;
        store_frag_pair((uchar*)g_xf + (size_t)tx * 65536, k, b, x[i]);
    }
    for (size_t i = tid; i < (size_t)H * DOUT; i += stride) {
        size_t k = i / DOUT, o = i % DOUT;
        g_WlinT[i] = Wlin[o * H + k];
    }
    for (size_t i = tid; i < G; i += stride) {
        g_b0[i] = bih0[i] + bhh0[i];
        g_b1[i] = bih1[i] + bhh1[i];
    }
    for (size_t i = tid; i < H * B; i += stride) {
        int u = i >> 6, b = i & 63;
        float zv = z[(size_t)b * H + u];
        store_frag_h((uchar*)g_h0f[0], u, b, zv);
        store_frag_h((uchar*)g_h1f[0], u, b, zv);
    }
}

// ---------------- xproj (bf16 3-term, unchanged from R10) ----------------
__global__ void __launch_bounds__(256, 1) xproj_kernel() {
    extern __shared__ uchar xs[];
    int t = blockIdx.y;
    int nb = blockIdx.x;             // 64-col group
    int tid = threadIdx.x;

    if (t == 0) {   // zero input step: bias only
        int n_local = tid >> 2, bb = (tid & 3) * 16;
        float bv = g_b0[nb * 64 + n_local];
        float4 v = make_float4(bv, bv, bv, bv);
        float4* dst = (float4*)&g_xp[(size_t)(nb * 64 + n_local) * B + bb];
        dst[0] = v; dst[1] = v; dst[2] = v; dst[3] = v;
        return;
    }

    unsigned sb = (unsigned)__cvta_generic_to_shared(xs);
    unsigned bar = sb + XS_BAR;
    if (tid == 0) {
        mbar_init(bar, 1);
        asm volatile("fence.proxy.async.shared::cta;" ::: "memory");
    }
    __syncthreads();
    if (tid == 0) {
        mbar_expect_tx(bar, 131072u);
        bulk_cp(sb + XS_A, (const uchar*)g_xf + (size_t)(t - 1) * 65536, 65536u, bar);
        bulk_cp(sb + XS_W, (const uchar*)g_WxF + (size_t)nb * 65536, 65536u, bar);
    }
    mbar_wait(bar, 0);

    int wid = tid >> 5, lane = tid & 31;
    int ksx = wid & 1, ngrp = (wid >> 1) & 1, mgrp = wid >> 2;
    float4 cacc[2][4];
#pragma unroll
    for (int i = 0; i < 2; i++)
#pragma unroll
        for (int j = 0; j < 4; j++) cacc[i][j] = make_float4(0.f, 0.f, 0.f, 0.f);

    const uchar* actb = xs + XS_A + ksx * 32768;
    const uchar* wtb  = xs + XS_W + ngrp * 32768 + ksx * 16384;
#pragma unroll
    for (int kt = 0; kt < 8; kt++)
        mma_kt(actb, wtb, kt, mgrp, lane, cacc);

    float* sgx = (float*)(xs + XS_S) + ksx * 4416;
#pragma unroll
    for (int mt = 0; mt < 2; mt++)
#pragma unroll
        for (int j = 0; j < 4; j++) {
            float4 v = cacc[mt][j];
            int row0 = mgrp * 32 + mt * 16 + (lane >> 2);
            int col = ngrp * 32 + j * 8 + (lane & 3) * 2;
            sgx[row0 * 69 + col] = v.x;
            sgx[row0 * 69 + col + 1] = v.y;
            sgx[(row0 + 8) * 69 + col] = v.z;
            sgx[(row0 + 8) * 69 + col + 1] = v.w;
        }
    __syncthreads();

    const float* sg0 = (const float*)(xs + XS_S);
    const float* sg1 = sg0 + 4416;
    int n_local = tid >> 2, bb = (tid & 3) * 16;
    float bv = g_b0[nb * 64 + n_local];
    float* dst = &g_xp[((size_t)t * G + nb * 64 + n_local) * B + bb];
#pragma unroll
    for (int q = 0; q < 4; q++) {
        float4 v;
        v.x = sg0[(bb + q * 4 + 0) * 69 + n_local] + sg1[(bb + q * 4 + 0) * 69 + n_local] + bv;
        v.y = sg0[(bb + q * 4 + 1) * 69 + n_local] + sg1[(bb + q * 4 + 1) * 69 + n_local] + bv;
        v.z = sg0[(bb + q * 4 + 2) * 69 + n_local] + sg1[(bb + q * 4 + 2) * 69 + n_local] + bv;
        v.w = sg0[(bb + q * 4 + 3) * 69 + n_local] + sg1[(bb + q * 4 + 3) * 69 + n_local] + bv;
        ((float4*)dst)[q] = v;
    }
}

// ---------------- persistent recurrent kernel ----------------
__device__ __forceinline__ void grid_sync(unsigned target) {
    __syncthreads();
    if (threadIdx.x == 0) {
        __threadfence();
        if (atomicAdd(&g_bar_cnt, 1u) == NBLK - 1) {
            g_bar_cnt = 0;
            __threadfence();
            g_bar_gen = target;
        } else {
            while (g_bar_gen < target) {}
            __threadfence();
        }
    }
    __syncthreads();
}

__device__ __forceinline__ void issue_stage(unsigned sb, int stage,
                                            const uchar* act, const uchar* wt) {
    unsigned bar = sb + S_BAR + stage * 8;
    mbar_expect_tx(bar, 32768u);
    bulk_cp(sb + stage * S_STAGE, act, 16384u, bar);
    bulk_cp(sb + stage * S_STAGE + 16384, wt, 16384u, bar);
}

__device__ __forceinline__ void chunk_src(int i, const uchar* h0src, const uchar* h1src,
                                          const uchar* wf0base, const uchar* wf1base,
                                          const uchar*& act, const uchar*& wt) {
    if (i < 16) {   // layer1 chunk
        act = (i < 8) ? h0src + (size_t)i * 16384 : h1src + (size_t)(i - 8) * 16384;
        wt = wf1base + (size_t)i * 16384;
    } else {        // layer0 (next step) chunk
        act = h0src + (size_t)(i - 16) * 16384;
        wt = wf0base + (size_t)(i - 16) * 16384;
    }
}

__global__ void __launch_bounds__(THR, 1) recur_kernel() {
    extern __shared__ uchar smem[];
    unsigned sb = (unsigned)__cvta_generic_to_shared(smem);
    float* sg4 = (float*)(smem + S_SG);

    int tid = threadIdx.x;
    int blk = blockIdx.x;
    int wrp = tid >> 5, lane = tid & 31;
    int ks = wrp & 3;          // K-split slice: handles kt = ks, ks+4
    int mgroup = wrp >> 2;     // batches mgroup*32 .. +31
    int u0 = blk * 8;

    // gate-phase ownership: 2 (unit,batch) items per thread
    int u_[2], b_[2];
    float b1v[2][4];
#pragma unroll
    for (int j = 0; j < 2; j++) {
        int item = tid + j * THR;
        u_[j] = item >> 6;
        b_[j] = item & 63;
#pragma unroll
        for (int g = 0; g < 4; g++)
            b1v[j][g] = g_b1[g * H + u0 + u_[j]];
    }

    if (tid == 0) {
        mbar_init(sb + S_BAR, 1);
        mbar_init(sb + S_BAR + 8, 1);
        mbar_init(sb + S_BAR + 16, 1);
        asm volatile("fence.proxy.async.shared::cta;" ::: "memory");
    }
    __syncthreads();

    unsigned ph_bits = 0;      // per-stage phase parity
    float c0r[2] = {0.0f, 0.0f};
    float c1r[2] = {0.0f, 0.0f};

    const uchar* wf0base = (const uchar*)&g_Wf0[(size_t)blk * 8 * 8192];
    const uchar* wf1base = (const uchar*)&g_Wf1[(size_t)blk * 16 * 8192];

    float4 acc0[2][4], acc1[2][4];

    // ================= prologue: L0(0) =================
    {
        const uchar* h00 = (const uchar*)g_h0f[0];
        if (tid == 0) {
            issue_stage(sb, 0, h00, wf0base);
            issue_stage(sb, 1, h00 + 16384, wf0base + 16384);
        }
#pragma unroll
        for (int i = 0; i < 2; i++)
#pragma unroll
            for (int j = 0; j < 4; j++) acc0[i][j] = make_float4(0.f, 0.f, 0.f, 0.f);
        for (int i = 0; i < 8; i++) {
            int stage = i % 3;
            if (tid == 0 && i + 2 < 8)
                issue_stage(sb, (i + 2) % 3, h00 + (size_t)(i + 2) * 16384,
                            wf0base + (size_t)(i + 2) * 16384);
            mbar_wait(sb + S_BAR + stage * 8, (ph_bits >> stage) & 1);
            ph_bits ^= 1u << stage;
            const uchar* actb = smem + stage * S_STAGE;
            const uchar* wtb = actb + 16384;
            mma_kt_h(actb, wtb, ks, mgroup, lane, acc0);
            mma_kt_h(actb, wtb, ks + 4, mgroup, lane, acc0);
            __syncthreads();
        }
        // L0(0) gates -> h0f[1]
        float* sgS = sg4 + ks * 2112;
#pragma unroll
        for (int mt = 0; mt < 2; mt++)
#pragma unroll
            for (int j = 0; j < 4; j++) {
                float4 v = acc0[mt][j];
                int row0 = mgroup * 32 + mt * 16 + (lane >> 2);
                int colb = j * 8 + (lane & 3) * 2;
                sgS[row0 * 33 + colb] = v.x;
                sgS[row0 * 33 + colb + 1] = v.y;
                sgS[(row0 + 8) * 33 + colb] = v.z;
                sgS[(row0 + 8) * 33 + colb + 1] = v.w;
            }
        __syncthreads();
#pragma unroll
        for (int j = 0; j < 2; j++) {
            int u = u_[j], b = b_[j];
            float gv[4];
#pragma unroll
            for (int g = 0; g < 4; g++) {
                float s = g_xp[((size_t)0 * G + g * H + u0 + u) * B + b];
#pragma unroll
                for (int sI = 0; sI < 4; sI++)
                    s += sg4[sI * 2112 + b * 33 + g * 8 + u];
                gv[g] = s;
            }
            float cc = sigm(gv[1]) * c0r[j] + sigm(gv[0]) * tanh_f(gv[2]);
            c0r[j] = cc;
            float h = sigm(gv[3]) * tanh_f(cc);
            store_frag_h((uchar*)g_h0f[1], u0 + u, b, h);
        }
    }

    // ================= main loop: one grid sync per step =================
    for (int t = 0; t < T; t++) {
        grid_sync(t + 1);
        const uchar* h0src = (const uchar*)g_h0f[(t + 1) & 1];  // h0(t)
        const uchar* h1src = (const uchar*)g_h1f[t & 1];        // h1(t-1)
        int NCH = (t == T - 1) ? 16 : 24;

        if (tid == 0) {
            const uchar *a0, *w0, *a1, *w1;
            chunk_src(0, h0src, h1src, wf0base, wf1base, a0, w0);
            chunk_src(1, h0src, h1src, wf0base, wf1base, a1, w1);
            issue_stage(sb, 0, a0, w0);
            issue_stage(sb, 1, a1, w1);
        }
#pragma unroll
        for (int i = 0; i < 2; i++)
#pragma unroll
            for (int j = 0; j < 4; j++) {
                acc1[i][j] = make_float4(0.f, 0.f, 0.f, 0.f);
                acc0[i][j] = make_float4(0.f, 0.f, 0.f, 0.f);
            }

        for (int i = 0; i < NCH; i++) {
            int stage = i % 3;
            if (tid == 0 && i + 2 < NCH) {
                const uchar *an, *wn;
                chunk_src(i + 2, h0src, h1src, wf0base, wf1base, an, wn);
                issue_stage(sb, (i + 2) % 3, an, wn);
            }
            mbar_wait(sb + S_BAR + stage * 8, (ph_bits >> stage) & 1);
            ph_bits ^= 1u << stage;
            const uchar* actb = smem + stage * S_STAGE;
            const uchar* wtb = actb + 16384;
            if (i < 16) {
                mma_kt_h(actb, wtb, ks, mgroup, lane, acc1);
                mma_kt_h(actb, wtb, ks + 4, mgroup, lane, acc1);
            } else {
                mma_kt_h(actb, wtb, ks, mgroup, lane, acc0);
                mma_kt_h(actb, wtb, ks + 4, mgroup, lane, acc0);
            }
            __syncthreads();

            if (i == 15) {
                // ---- L1(t) gates interleaved: TMA for L0 chunks continues ----
                {
                    float* sgS = sg4 + ks * 2112;
#pragma unroll
                    for (int mt = 0; mt < 2; mt++)
#pragma unroll
                        for (int j = 0; j < 4; j++) {
                            float4 v = acc1[mt][j];
                            int row0 = mgroup * 32 + mt * 16 + (lane >> 2);
                            int colb = j * 8 + (lane & 3) * 2;
                            sgS[row0 * 33 + colb] = v.x;
                            sgS[row0 * 33 + colb + 1] = v.y;
                            sgS[(row0 + 8) * 33 + colb] = v.z;
                            sgS[(row0 + 8) * 33 + colb + 1] = v.w;
                        }
                }
                __syncthreads();
#pragma unroll
                for (int j = 0; j < 2; j++) {
                    int u = u_[j], b = b_[j];
                    float gv[4];
#pragma unroll
                    for (int g = 0; g < 4; g++) {
                        float s = b1v[j][g];
#pragma unroll
                        for (int sI = 0; sI < 4; sI++)
                            s += sg4[sI * 2112 + b * 33 + g * 8 + u];
                        gv[g] = s;
                    }
                    float cc = sigm(gv[1]) * c1r[j] + sigm(gv[0]) * tanh_f(gv[2]);
                    c1r[j] = cc;
                    float h = sigm(gv[3]) * tanh_f(cc);
                    store_frag_h((uchar*)g_h1f[(t + 1) & 1], u0 + u, b, h);
                    g_h1buf[(size_t)t * H * B + (u0 + u) * B + b] = h;
                }
                __syncthreads();   // protect sg4 before L0 gate staging reuses it
            }
        }

        // ---- L0(t+1) gates -> h0f[t&1] ----
        if (t + 1 < T) {
            {
                float* sgS = sg4 + ks * 2112;
#pragma unroll
                for (int mt = 0; mt < 2; mt++)
#pragma unroll
                    for (int j = 0; j < 4; j++) {
                        float4 v = acc0[mt][j];
                        int row0 = mgroup * 32 + mt * 16 + (lane >> 2);
                        int colb = j * 8 + (lane & 3) * 2;
                        sgS[row0 * 33 + colb] = v.x;
                        sgS[row0 * 33 + colb + 1] = v.y;
                        sgS[(row0 + 8) * 33 + colb] = v.z;
                        sgS[(row0 + 8) * 33 + colb + 1] = v.w;
                    }
            }
            __syncthreads();
#pragma unroll
            for (int j = 0; j < 2; j++) {
                int u = u_[j], b = b_[j];
                float gv[4];
#pragma unroll
                for (int g = 0; g < 4; g++) {
                    float s = g_xp[((size_t)(t + 1) * G + g * H + u0 + u) * B + b];
#pragma unroll
                    for (int sI = 0; sI < 4; sI++)
                        s += sg4[sI * 2112 + b * 33 + g * 8 + u];
                    gv[g] = s;
                }
                float cc = sigm(gv[1]) * c0r[j] + sigm(gv[0]) * tanh_f(gv[2]);
                c0r[j] = cc;
                float h = sigm(gv[3]) * tanh_f(cc);
                store_frag_h((uchar*)g_h0f[t & 1], u0 + u, b, h);
            }
        }
    }
}

// ---------------- out: out[b][t][o] = blin[o] + sum_k h1buf[t][k][b] * WlinT[k][o] ----------------
__global__ __launch_bounds__(256) void out_kernel(const float* __restrict__ blin,
                                                  float* __restrict__ out) {
    int t = blockIdx.y;
    int o0 = blockIdx.x * 64;
    int tid = threadIdx.x;
    int w = tid >> 5, l = tid & 31;

    __shared__ float sh[64 * 64];   // [k][b]
    float acc0[8], acc1[8];
#pragma unroll
    for (int i = 0; i < 8; i++) { acc0[i] = 0.0f; acc1[i] = 0.0f; }

    for (int k0 = 0; k0 < H; k0 += 64) {
        __syncthreads();
#pragma unroll
        for (int r = 0; r < 4; r++) {
            int idx = tid + r * 256;
            ((float4*)sh)[idx] =
                *(((const float4*)&g_h1buf[((size_t)t * H + k0) * B]) + idx);
        }
        __syncthreads();
#pragma unroll 8
        for (int kk = 0; kk < 64; kk++) {
            const float* wr = &g_WlinT[(size_t)(k0 + kk) * DOUT + o0];
            float wa = wr[l];
            float wb = wr[32 + l];
#pragma unroll
            for (int i = 0; i < 8; i++) {
                float av = sh[kk * 64 + w * 8 + i];
                acc0[i] += wa * av;
                acc1[i] += wb * av;
            }
        }
    }
    float ba = blin[o0 + l], bb = blin[o0 + 32 + l];
#pragma unroll
    for (int i = 0; i < 8; i++) {
        int b = w * 8 + i;
        size_t base = ((size_t)b * T + t) * DOUT + o0;
        out[base + l] = acc0[i] + ba;
        out[base + 32 + l] = acc1[i] + bb;
    }
}

// ---------------- launch ----------------
extern "C" void kernel_launch(void* const* d_in, const int* in_sizes, int n_in,
                              void* d_out, int out_size) {
    const float* z    = (const float*)d_in[0];
    const float* x    = (const float*)d_in[1];
    const float* Wih0 = (const float*)d_in[2];
    const float* Whh0 = (const float*)d_in[3];
    const float* bih0 = (const float*)d_in[4];
    const float* bhh0 = (const float*)d_in[5];
    const float* Wih1 = (const float*)d_in[6];
    const float* Whh1 = (const float*)d_in[7];
    const float* bih1 = (const float*)d_in[8];
    const float* bhh1 = (const float*)d_in[9];
    const float* Wlin = (const float*)d_in[10];
    const float* blin = (const float*)d_in[11];
    float* out = (float*)d_out;

    cudaFuncSetAttribute(recur_kernel, cudaFuncAttributeMaxDynamicSharedMemorySize,
                         SMEM_BYTES);
    cudaFuncSetAttribute(xproj_kernel, cudaFuncAttributeMaxDynamicSharedMemorySize,
                         XSMEM_BYTES);

    prep_kernel<<<512, 256>>>(z, x, Wih0, Whh0, bih0, bhh0, Wih1, Whh1, bih1, bhh1, Wlin);
    xproj_kernel<<<dim3(G / 64, T), 256, XSMEM_BYTES>>>();
    recur_kernel<<<NBLK, THR, SMEM_BYTES>>>();
    out_kernel<<<dim3(DOUT / 64, T), 256>>>(blin, out);
}

// round 16
// speedup vs baseline: 2.1279x; 1.2020x over previous
#include <cuda_runtime.h>
#include <cuda_bf16.h>
#include <cuda_fp16.h>
#include <cstdint>

#define B    64
#define T    512
#define DIN  256
#define H    1024
#define G    4096   // 4*H
#define DOUT 256
#define NBLK 128
#define THR  256

typedef unsigned long long ull;
typedef unsigned char uchar;

// ---------------- recur SMEM byte layout: 3 stages x (16KB act + 8KB wt) ----------------
#define S_STAGE  24576
#define S_SG     73728               // 4 slices x 2112 floats = 33792 B
#define S_BAR    107520              // 3 mbarriers
#define SMEM_BYTES 107552

// ---------------- xproj SMEM byte layout (bf16 path, unchanged) ----------------
#define XS_A    0                    // 2 chunks x 32768
#define XS_W    65536                // 2 ngrp x (2 chunks x 16384)
#define XS_S    131072               // 2 slices x 4416 floats = 35328 B
#define XS_BAR  166400
#define XSMEM_BYTES 166432

// ---------------- device scratch ----------------
__device__ __align__(128) unsigned short g_Wf0[(size_t)NBLK * 8 * 4096];   // layer0 fp16 frag (single plane)
__device__ __align__(128) unsigned short g_Wf1[(size_t)NBLK * 16 * 4096];  // layer1
__device__ __align__(128) unsigned short g_WxF[(size_t)128 * 2 * 8192];    // xproj weights frag (bf16 hi/lo)
__device__ __align__(128) unsigned short g_xf[(size_t)T * 32768];          // x frag (bf16 hi/lo)
__device__ float g_WlinT[(size_t)H * DOUT];       // [k][o]
__device__ float g_b0[G];
__device__ float g_b1[G];
__device__ float g_xp[(size_t)T * G * B];         // [t][n][b]
__device__ __align__(128) unsigned short g_h0f[2][65536];   // fp16 acts: 8 chunks x 16KB
__device__ __align__(128) unsigned short g_h1f[2][65536];
__device__ float g_h1buf[(size_t)T * H * B];      // [t][u][b] fp32 for out

__device__ volatile unsigned g_bar_gen;
__device__ unsigned g_bar_cnt;

// ---------------- helpers ----------------
__device__ __forceinline__ float sigm(float x) { return 1.0f / (1.0f + __expf(-x)); }
__device__ __forceinline__ float tanh_f(float x) {
    float e = __expf(-2.0f * fabsf(x));
    float t = (1.0f - e) / (1.0f + e);
    return x >= 0.0f ? t : -t;
}
__device__ __forceinline__ void mbar_init(unsigned mbar, unsigned cnt) {
    asm volatile("mbarrier.init.shared.b64 [%0], %1;" :: "r"(mbar), "r"(cnt) : "memory");
}
__device__ __forceinline__ void mbar_expect_tx(unsigned mbar, unsigned bytes) {
    asm volatile("mbarrier.arrive.expect_tx.shared.b64 _, [%0], %1;" :: "r"(mbar), "r"(bytes) : "memory");
}
__device__ __forceinline__ void mbar_wait(unsigned mbar, unsigned phase) {
    asm volatile(
        "{\n\t"
        ".reg .pred P;\n\t"
        "WAIT_%=:\n\t"
        "mbarrier.try_wait.parity.acquire.cta.shared::cta.b64 P, [%0], %1, 0x989680;\n\t"
        "@P bra.uni DONE_%=;\n\t"
        "bra.uni WAIT_%=;\n\t"
        "DONE_%=:\n\t"
        "}"
        :: "r"(mbar), "r"(phase) : "memory");
}
__device__ __forceinline__ void bulk_cp(unsigned dst, const void* src, unsigned bytes, unsigned mbar) {
    asm volatile(
        "cp.async.bulk.shared::cluster.global.mbarrier::complete_tx::bytes [%0], [%1], %2, [%3];"
        :: "r"(dst), "l"(src), "r"(bytes), "r"(mbar) : "memory");
}
// bf16 mma (xproj path)
__device__ __forceinline__ void mma16816(float4& d, const uint4& a, unsigned b0, unsigned b1) {
    asm volatile("mma.sync.aligned.m16n8k16.row.col.f32.bf16.bf16.f32 "
                 "{%0,%1,%2,%3}, {%4,%5,%6,%7}, {%8,%9}, {%0,%1,%2,%3};"
                 : "+f"(d.x), "+f"(d.y), "+f"(d.z), "+f"(d.w)
                 : "r"(a.x), "r"(a.y), "r"(a.z), "r"(a.w), "r"(b0), "r"(b1));
}
// fp16 mma (recur path)
__device__ __forceinline__ void hmma16816(float4& d, const uint4& a, unsigned b0, unsigned b1) {
    asm volatile("mma.sync.aligned.m16n8k16.row.col.f32.f16.f16.f32 "
                 "{%0,%1,%2,%3}, {%4,%5,%6,%7}, {%8,%9}, {%0,%1,%2,%3};"
                 : "+f"(d.x), "+f"(d.y), "+f"(d.z), "+f"(d.w)
                 : "r"(a.x), "r"(a.y), "r"(a.z), "r"(a.w), "r"(b0), "r"(b1));
}

// ---- bf16 hi/lo frag store (xproj x packing only; 32KB chunks) ----
__device__ __forceinline__ void store_frag_pair(uchar* basearr, int uGlob, int b, float v) {
    int chunk = uGlob >> 7, kl = uGlob & 127;
    int kt = kl >> 4, kk = kl & 15;
    int mt = b >> 4, mm = b & 15;
    int reg = ((kk & 8) >> 2) | ((mm & 8) >> 3);
    int lane = (mm & 7) * 4 + ((kk & 7) >> 1);
    int half = kk & 1;
    int off = kt * 2048 + mt * 512 + lane * 16 + reg * 4 + half * 2;
    __nv_bfloat16 hb = __float2bfloat16_rn(v);
    float hf = __bfloat162float(hb);
    __nv_bfloat16 lb = __float2bfloat16_rn(v - hf);
    uchar* p = basearr + (size_t)chunk * 32768 + off;
    *(__nv_bfloat16*)p = hb;
    *(__nv_bfloat16*)(p + 16384) = lb;
}
// ---- fp16 single-plane frag store (recur acts; 16KB chunks) ----
__device__ __forceinline__ void store_frag_h(uchar* basearr, int uGlob, int b, float v) {
    int chunk = uGlob >> 7, kl = uGlob & 127;
    int kt = kl >> 4, kk = kl & 15;
    int mt = b >> 4, mm = b & 15;
    int reg = ((kk & 8) >> 2) | ((mm & 8) >> 3);
    int lane = (mm & 7) * 4 + ((kk & 7) >> 1);
    int half = kk & 1;
    int off = kt * 2048 + mt * 512 + lane * 16 + reg * 4 + half * 2;
    *(__half*)(basearr + (size_t)chunk * 16384 + off) = __float2half_rn(v);
}

// bf16 3-term k16-step (xproj path; act chunk 32KB hi/lo, wt chunk 16KB hi/lo)
__device__ __forceinline__ void mma_kt(const uchar* actb, const uchar* wtb,
                                       int kt, int mgroup, int lane, float4 (&c)[2][4]) {
    const uchar* ab = actb + kt * 2048 + lane * 16;
    uint4 ah0 = *(const uint4*)(ab + (mgroup * 2 + 0) * 512);
    uint4 ah1 = *(const uint4*)(ab + (mgroup * 2 + 1) * 512);
    uint4 al0 = *(const uint4*)(ab + 16384 + (mgroup * 2 + 0) * 512);
    uint4 al1 = *(const uint4*)(ab + 16384 + (mgroup * 2 + 1) * 512);
    const uchar* wb = wtb + kt * 2048 + lane * 16;
    uint4 bh0 = *(const uint4*)(wb);
    uint4 bl0 = *(const uint4*)(wb + 512);
    uint4 bh1 = *(const uint4*)(wb + 1024);
    uint4 bl1 = *(const uint4*)(wb + 1536);
    mma16816(c[0][0], ah0, bh0.x, bh0.y);  mma16816(c[1][0], ah1, bh0.x, bh0.y);
    mma16816(c[0][1], ah0, bh0.z, bh0.w);  mma16816(c[1][1], ah1, bh0.z, bh0.w);
    mma16816(c[0][2], ah0, bh1.x, bh1.y);  mma16816(c[1][2], ah1, bh1.x, bh1.y);
    mma16816(c[0][3], ah0, bh1.z, bh1.w);  mma16816(c[1][3], ah1, bh1.z, bh1.w);
    mma16816(c[0][0], ah0, bl0.x, bl0.y);  mma16816(c[1][0], ah1, bl0.x, bl0.y);
    mma16816(c[0][1], ah0, bl0.z, bl0.w);  mma16816(c[1][1], ah1, bl0.z, bl0.w);
    mma16816(c[0][2], ah0, bl1.x, bl1.y);  mma16816(c[1][2], ah1, bl1.x, bl1.y);
    mma16816(c[0][3], ah0, bl1.z, bl1.w);  mma16816(c[1][3], ah1, bl1.z, bl1.w);
    mma16816(c[0][0], al0, bh0.x, bh0.y);  mma16816(c[1][0], al1, bh0.x, bh0.y);
    mma16816(c[0][1], al0, bh0.z, bh0.w);  mma16816(c[1][1], al1, bh0.z, bh0.w);
    mma16816(c[0][2], al0, bh1.x, bh1.y);  mma16816(c[1][2], al1, bh1.x, bh1.y);
    mma16816(c[0][3], al0, bh1.z, bh1.w);  mma16816(c[1][3], al1, bh1.z, bh1.w);
}

// fp16 single-term k16-step (recur path; act chunk 16KB, wt chunk 8KB)
__device__ __forceinline__ void mma_kt_h(const uchar* actb, const uchar* wtb,
                                         int kt, int mgroup, int lane, float4 (&c)[2][4]) {
    const uchar* ab = actb + kt * 2048 + lane * 16;
    uint4 a0 = *(const uint4*)(ab + (mgroup * 2 + 0) * 512);
    uint4 a1 = *(const uint4*)(ab + (mgroup * 2 + 1) * 512);
    const uchar* wb = wtb + kt * 1024 + lane * 16;
    uint4 b0 = *(const uint4*)(wb);          // nt0: n8#0 (x,y), n8#1 (z,w)
    uint4 b1 = *(const uint4*)(wb + 512);    // nt1: n8#2, n8#3
    hmma16816(c[0][0], a0, b0.x, b0.y);  hmma16816(c[1][0], a1, b0.x, b0.y);
    hmma16816(c[0][1], a0, b0.z, b0.w);  hmma16816(c[1][1], a1, b0.z, b0.w);
    hmma16816(c[0][2], a0, b1.x, b1.y);  hmma16816(c[1][2], a1, b1.x, b1.y);
    hmma16816(c[0][3], a0, b1.z, b1.w);  hmma16816(c[1][3], a1, b1.z, b1.w);
}

// ---------------- prep ----------------
__global__ void prep_kernel(const float* __restrict__ z, const float* __restrict__ x,
                            const float* __restrict__ Wih0, const float* __restrict__ Whh0,
                            const float* __restrict__ bih0, const float* __restrict__ bhh0,
                            const float* __restrict__ Wih1, const float* __restrict__ Whh1,
                            const float* __restrict__ bih1, const float* __restrict__ bhh1,
                            const float* __restrict__ Wlin) {
    size_t stride = (size_t)gridDim.x * blockDim.x;
    size_t tid = (size_t)blockIdx.x * blockDim.x + threadIdx.x;
    if (tid == 0) { g_bar_gen = 0; g_bar_cnt = 0; }

    // layer0 frag weights (fp16 single plane): bits half(1) slotq(2) lane(5) nt(1) kt(3) chunk(3) blk
    for (size_t e = tid; e < (size_t)NBLK * 8 * 4096; e += stride) {
        int half = e & 1;
        int slotq = (e >> 1) & 3;
        int lane = (e >> 3) & 31;
        int nt = (e >> 8) & 1;
        int kt = (e >> 9) & 7;
        int chunk = (e >> 12) & 7;
        size_t blk = e >> 15;
        int n8sel = slotq >> 1, kHi = slotq & 1;
        int nn = lane >> 2, tig = lane & 3;
        int kk = kHi * 8 + tig * 2 + half;
        int k = chunk * 128 + kt * 16 + kk;
        int cc = nt * 16 + n8sel * 8 + nn;
        size_t n = (size_t)(cc >> 3) * H + blk * 8 + (cc & 7);
        __half outv = __float2half_rn(Whh0[n * H + k]);
        g_Wf0[e] = *(unsigned short*)&outv;
    }
    // layer1 frag weights (K = 2048: first h0, then h1)
    for (size_t e = tid; e < (size_t)NBLK * 16 * 4096; e += stride) {
        int half = e & 1;
        int slotq = (e >> 1) & 3;
        int lane = (e >> 3) & 31;
        int nt = (e >> 8) & 1;
        int kt = (e >> 9) & 7;
        int chunk = (e >> 12) & 15;
        size_t blk = e >> 16;
        int n8sel = slotq >> 1, kHi = slotq & 1;
        int nn = lane >> 2, tig = lane & 3;
        int kk = kHi * 8 + tig * 2 + half;
        int k = chunk * 128 + kt * 16 + kk;
        int cc = nt * 16 + n8sel * 8 + nn;
        size_t n = (size_t)(cc >> 3) * H + blk * 8 + (cc & 7);
        float w = (k < H) ? Wih1[n * H + k] : Whh1[n * H + (k - H)];
        __half outv = __float2half_rn(w);
        g_Wf1[e] = *(unsigned short*)&outv;
    }
    // xproj frag weights (bf16 hi/lo, unchanged)
    for (size_t e = tid; e < (size_t)128 * 2 * 8192; e += stride) {
        int half = e & 1;
        int slotq = (e >> 1) & 3;
        int lane = (e >> 3) & 31;
        int hl = (e >> 8) & 1;
        int nt = (e >> 9) & 1;
        int kt = (e >> 10) & 7;
        int chunk = (e >> 13) & 1;
        size_t nb32 = e >> 14;
        int n8sel = slotq >> 1, kHi = slotq & 1;
        int nn = lane >> 2, tig = lane & 3;
        int kk = kHi * 8 + tig * 2 + half;
        int k = chunk * 128 + kt * 16 + kk;
        size_t n = nb32 * 32 + nt * 16 + n8sel * 8 + nn;
        float w = Wih0[n * DIN + k];
        __nv_bfloat16 hb = __float2bfloat16_rn(w);
        __nv_bfloat16 outv = hb;
        if (hl) outv = __float2bfloat16_rn(w - __bfloat162float(hb));
        g_WxF[e] = *(unsigned short*)&outv;
    }
    // x frag pack (bf16 hi/lo)
    for (size_t i = tid; i < (size_t)T * B * DIN; i += stride) {
        int k = i & 255;
        int tx = (i >> 8) & (T - 1);
        int b = i >> 17;
        store_frag_pair((uchar*)g_xf + (size_t)tx * 65536, k, b, x[i]);
    }
    for (size_t i = tid; i < (size_t)H * DOUT; i += stride) {
        size_t k = i / DOUT, o = i % DOUT;
        g_WlinT[i] = Wlin[o * H + k];
    }
    for (size_t i = tid; i < G; i += stride) {
        g_b0[i] = bih0[i] + bhh0[i];
        g_b1[i] = bih1[i] + bhh1[i];
    }
    for (size_t i = tid; i < H * B; i += stride) {
        int u = i >> 6, b = i & 63;
        float zv = z[(size_t)b * H + u];
        store_frag_h((uchar*)g_h0f[0], u, b, zv);
        store_frag_h((uchar*)g_h1f[0], u, b, zv);
    }
}

// ---------------- xproj (bf16 3-term, unchanged from R10) ----------------
__global__ void __launch_bounds__(256, 1) xproj_kernel() {
    extern __shared__ uchar xs[];
    int t = blockIdx.y;
    int nb = blockIdx.x;             // 64-col group
    int tid = threadIdx.x;

    if (t == 0) {   // zero input step: bias only
        int n_local = tid >> 2, bb = (tid & 3) * 16;
        float bv = g_b0[nb * 64 + n_local];
        float4 v = make_float4(bv, bv, bv, bv);
        float4* dst = (float4*)&g_xp[(size_t)(nb * 64 + n_local) * B + bb];
        dst[0] = v; dst[1] = v; dst[2] = v; dst[3] = v;
        return;
    }

    unsigned sb = (unsigned)__cvta_generic_to_shared(xs);
    unsigned bar = sb + XS_BAR;
    if (tid == 0) {
        mbar_init(bar, 1);
        asm volatile("fence.proxy.async.shared::cta;" ::: "memory");
    }
    __syncthreads();
    if (tid == 0) {
        mbar_expect_tx(bar, 131072u);
        bulk_cp(sb + XS_A, (const uchar*)g_xf + (size_t)(t - 1) * 65536, 65536u, bar);
        bulk_cp(sb + XS_W, (const uchar*)g_WxF + (size_t)nb * 65536, 65536u, bar);
    }
    mbar_wait(bar, 0);

    int wid = tid >> 5, lane = tid & 31;
    int ksx = wid & 1, ngrp = (wid >> 1) & 1, mgrp = wid >> 2;
    float4 cacc[2][4];
#pragma unroll
    for (int i = 0; i < 2; i++)
#pragma unroll
        for (int j = 0; j < 4; j++) cacc[i][j] = make_float4(0.f, 0.f, 0.f, 0.f);

    const uchar* actb = xs + XS_A + ksx * 32768;
    const uchar* wtb  = xs + XS_W + ngrp * 32768 + ksx * 16384;
#pragma unroll
    for (int kt = 0; kt < 8; kt++)
        mma_kt(actb, wtb, kt, mgrp, lane, cacc);

    float* sgx = (float*)(xs + XS_S) + ksx * 4416;
#pragma unroll
    for (int mt = 0; mt < 2; mt++)
#pragma unroll
        for (int j = 0; j < 4; j++) {
            float4 v = cacc[mt][j];
            int row0 = mgrp * 32 + mt * 16 + (lane >> 2);
            int col = ngrp * 32 + j * 8 + (lane & 3) * 2;
            sgx[row0 * 69 + col] = v.x;
            sgx[row0 * 69 + col + 1] = v.y;
            sgx[(row0 + 8) * 69 + col] = v.z;
            sgx[(row0 + 8) * 69 + col + 1] = v.w;
        }
    __syncthreads();

    const float* sg0 = (const float*)(xs + XS_S);
    const float* sg1 = sg0 + 4416;
    int n_local = tid >> 2, bb = (tid & 3) * 16;
    float bv = g_b0[nb * 64 + n_local];
    float* dst = &g_xp[((size_t)t * G + nb * 64 + n_local) * B + bb];
#pragma unroll
    for (int q = 0; q < 4; q++) {
        float4 v;
        v.x = sg0[(bb + q * 4 + 0) * 69 + n_local] + sg1[(bb + q * 4 + 0) * 69 + n_local] + bv;
        v.y = sg0[(bb + q * 4 + 1) * 69 + n_local] + sg1[(bb + q * 4 + 1) * 69 + n_local] + bv;
        v.z = sg0[(bb + q * 4 + 2) * 69 + n_local] + sg1[(bb + q * 4 + 2) * 69 + n_local] + bv;
        v.w = sg0[(bb + q * 4 + 3) * 69 + n_local] + sg1[(bb + q * 4 + 3) * 69 + n_local] + bv;
        ((float4*)dst)[q] = v;
    }
}

// ---------------- persistent recurrent kernel ----------------
__device__ __forceinline__ void grid_sync(unsigned target) {
    __syncthreads();
    if (threadIdx.x == 0) {
        __threadfence();
        if (atomicAdd(&g_bar_cnt, 1u) == NBLK - 1) {
            g_bar_cnt = 0;
            __threadfence();
            g_bar_gen = target;
        } else {
            while (g_bar_gen < target) {}
            __threadfence();
        }
    }
    __syncthreads();
}

__device__ __forceinline__ void issue_stage(unsigned sb, int stage,
                                            const uchar* act, const uchar* wt) {
    unsigned bar = sb + S_BAR + stage * 8;
    mbar_expect_tx(bar, 24576u);
    bulk_cp(sb + stage * S_STAGE, act, 16384u, bar);
    bulk_cp(sb + stage * S_STAGE + 16384, wt, 8192u, bar);
}

__device__ __forceinline__ void chunk_src(int i, const uchar* h0src, const uchar* h1src,
                                          const uchar* wf0base, const uchar* wf1base,
                                          const uchar*& act, const uchar*& wt) {
    if (i < 16) {   // layer1 chunk
        act = (i < 8) ? h0src + (size_t)i * 16384 : h1src + (size_t)(i - 8) * 16384;
        wt = wf1base + (size_t)i * 8192;
    } else {        // layer0 (next step) chunk
        act = h0src + (size_t)(i - 16) * 16384;
        wt = wf0base + (size_t)(i - 16) * 8192;
    }
}

__global__ void __launch_bounds__(THR, 1) recur_kernel() {
    extern __shared__ uchar smem[];
    unsigned sb = (unsigned)__cvta_generic_to_shared(smem);
    float* sg4 = (float*)(smem + S_SG);

    int tid = threadIdx.x;
    int blk = blockIdx.x;
    int wrp = tid >> 5, lane = tid & 31;
    int ks = wrp & 3;          // K-split slice: handles kt = ks, ks+4
    int mgroup = wrp >> 2;     // batches mgroup*32 .. +31
    int u0 = blk * 8;

    // gate-phase ownership: 2 (unit,batch) items per thread
    int u_[2], b_[2];
    float b1v[2][4];
#pragma unroll
    for (int j = 0; j < 2; j++) {
        int item = tid + j * THR;
        u_[j] = item >> 6;
        b_[j] = item & 63;
#pragma unroll
        for (int g = 0; g < 4; g++)
            b1v[j][g] = g_b1[g * H + u0 + u_[j]];
    }

    if (tid == 0) {
        mbar_init(sb + S_BAR, 1);
        mbar_init(sb + S_BAR + 8, 1);
        mbar_init(sb + S_BAR + 16, 1);
        asm volatile("fence.proxy.async.shared::cta;" ::: "memory");
    }
    __syncthreads();

    unsigned ph_bits = 0;      // per-stage phase parity
    float c0r[2] = {0.0f, 0.0f};
    float c1r[2] = {0.0f, 0.0f};

    const uchar* wf0base = (const uchar*)&g_Wf0[(size_t)blk * 8 * 4096];
    const uchar* wf1base = (const uchar*)&g_Wf1[(size_t)blk * 16 * 4096];

    float4 acc0[2][4], acc1[2][4];

    // ================= prologue: L0(0) =================
    {
        const uchar* h00 = (const uchar*)g_h0f[0];
        if (tid == 0) {
            issue_stage(sb, 0, h00, wf0base);
            issue_stage(sb, 1, h00 + 16384, wf0base + 8192);
        }
#pragma unroll
        for (int i = 0; i < 2; i++)
#pragma unroll
            for (int j = 0; j < 4; j++) acc0[i][j] = make_float4(0.f, 0.f, 0.f, 0.f);
        for (int i = 0; i < 8; i++) {
            int stage = i % 3;
            if (tid == 0 && i + 2 < 8)
                issue_stage(sb, (i + 2) % 3, h00 + (size_t)(i + 2) * 16384,
                            wf0base + (size_t)(i + 2) * 8192);
            mbar_wait(sb + S_BAR + stage * 8, (ph_bits >> stage) & 1);
            ph_bits ^= 1u << stage;
            const uchar* actb = smem + stage * S_STAGE;
            const uchar* wtb = actb + 16384;
            mma_kt_h(actb, wtb, ks, mgroup, lane, acc0);
            mma_kt_h(actb, wtb, ks + 4, mgroup, lane, acc0);
            __syncthreads();
        }
        // L0(0) gates -> h0f[1]
        float* sgS = sg4 + ks * 2112;
#pragma unroll
        for (int mt = 0; mt < 2; mt++)
#pragma unroll
            for (int j = 0; j < 4; j++) {
                float4 v = acc0[mt][j];
                int row0 = mgroup * 32 + mt * 16 + (lane >> 2);
                int colb = j * 8 + (lane & 3) * 2;
                sgS[row0 * 33 + colb] = v.x;
                sgS[row0 * 33 + colb + 1] = v.y;
                sgS[(row0 + 8) * 33 + colb] = v.z;
                sgS[(row0 + 8) * 33 + colb + 1] = v.w;
            }
        __syncthreads();
#pragma unroll
        for (int j = 0; j < 2; j++) {
            int u = u_[j], b = b_[j];
            float gv[4];
#pragma unroll
            for (int g = 0; g < 4; g++) {
                float s = g_xp[((size_t)0 * G + g * H + u0 + u) * B + b];
#pragma unroll
                for (int sI = 0; sI < 4; sI++)
                    s += sg4[sI * 2112 + b * 33 + g * 8 + u];
                gv[g] = s;
            }
            float cc = sigm(gv[1]) * c0r[j] + sigm(gv[0]) * tanh_f(gv[2]);
            c0r[j] = cc;
            float h = sigm(gv[3]) * tanh_f(cc);
            store_frag_h((uchar*)g_h0f[1], u0 + u, b, h);
        }
    }

    // ================= main loop: one grid sync per step =================
    for (int t = 0; t < T; t++) {
        grid_sync(t + 1);
        const uchar* h0src = (const uchar*)g_h0f[(t + 1) & 1];  // h0(t)
        const uchar* h1src = (const uchar*)g_h1f[t & 1];        // h1(t-1)
        int NCH = (t == T - 1) ? 16 : 24;

        if (tid == 0) {
            const uchar *a0, *w0, *a1, *w1;
            chunk_src(0, h0src, h1src, wf0base, wf1base, a0, w0);
            chunk_src(1, h0src, h1src, wf0base, wf1base, a1, w1);
            issue_stage(sb, 0, a0, w0);
            issue_stage(sb, 1, a1, w1);
        }
#pragma unroll
        for (int i = 0; i < 2; i++)
#pragma unroll
            for (int j = 0; j < 4; j++) {
                acc1[i][j] = make_float4(0.f, 0.f, 0.f, 0.f);
                acc0[i][j] = make_float4(0.f, 0.f, 0.f, 0.f);
            }

        for (int i = 0; i < NCH; i++) {
            int stage = i % 3;
            if (tid == 0 && i + 2 < NCH) {
                const uchar *an, *wn;
                chunk_src(i + 2, h0src, h1src, wf0base, wf1base, an, wn);
                issue_stage(sb, (i + 2) % 3, an, wn);
            }
            mbar_wait(sb + S_BAR + stage * 8, (ph_bits >> stage) & 1);
            ph_bits ^= 1u << stage;
            const uchar* actb = smem + stage * S_STAGE;
            const uchar* wtb = actb + 16384;
            if (i < 16) {
                mma_kt_h(actb, wtb, ks, mgroup, lane, acc1);
                mma_kt_h(actb, wtb, ks + 4, mgroup, lane, acc1);
            } else {
                mma_kt_h(actb, wtb, ks, mgroup, lane, acc0);
                mma_kt_h(actb, wtb, ks + 4, mgroup, lane, acc0);
            }
            __syncthreads();

            if (i == 15) {
                // ---- L1(t) gates interleaved: TMA for L0 chunks continues ----
                {
                    float* sgS = sg4 + ks * 2112;
#pragma unroll
                    for (int mt = 0; mt < 2; mt++)
#pragma unroll
                        for (int j = 0; j < 4; j++) {
                            float4 v = acc1[mt][j];
                            int row0 = mgroup * 32 + mt * 16 + (lane >> 2);
                            int colb = j * 8 + (lane & 3) * 2;
                            sgS[row0 * 33 + colb] = v.x;
                            sgS[row0 * 33 + colb + 1] = v.y;
                            sgS[(row0 + 8) * 33 + colb] = v.z;
                            sgS[(row0 + 8) * 33 + colb + 1] = v.w;
                        }
                }
                __syncthreads();
#pragma unroll
                for (int j = 0; j < 2; j++) {
                    int u = u_[j], b = b_[j];
                    float gv[4];
#pragma unroll
                    for (int g = 0; g < 4; g++) {
                        float s = b1v[j][g];
#pragma unroll
                        for (int sI = 0; sI < 4; sI++)
                            s += sg4[sI * 2112 + b * 33 + g * 8 + u];
                        gv[g] = s;
                    }
                    float cc = sigm(gv[1]) * c1r[j] + sigm(gv[0]) * tanh_f(gv[2]);
                    c1r[j] = cc;
                    float h = sigm(gv[3]) * tanh_f(cc);
                    store_frag_h((uchar*)g_h1f[(t + 1) & 1], u0 + u, b, h);
                    g_h1buf[(size_t)t * H * B + (u0 + u) * B + b] = h;
                }
                __syncthreads();   // protect sg4 before L0 gate staging reuses it
            }
        }

        // ---- L0(t+1) gates -> h0f[t&1] ----
        if (t + 1 < T) {
            {
                float* sgS = sg4 + ks * 2112;
#pragma unroll
                for (int mt = 0; mt < 2; mt++)
#pragma unroll
                    for (int j = 0; j < 4; j++) {
                        float4 v = acc0[mt][j];
                        int row0 = mgroup * 32 + mt * 16 + (lane >> 2);
                        int colb = j * 8 + (lane & 3) * 2;
                        sgS[row0 * 33 + colb] = v.x;
                        sgS[row0 * 33 + colb + 1] = v.y;
                        sgS[(row0 + 8) * 33 + colb] = v.z;
                        sgS[(row0 + 8) * 33 + colb + 1] = v.w;
                    }
            }
            __syncthreads();
#pragma unroll
            for (int j = 0; j < 2; j++) {
                int u = u_[j], b = b_[j];
                float gv[4];
#pragma unroll
                for (int g = 0; g < 4; g++) {
                    float s = g_xp[((size_t)(t + 1) * G + g * H + u0 + u) * B + b];
#pragma unroll
                    for (int sI = 0; sI < 4; sI++)
                        s += sg4[sI * 2112 + b * 33 + g * 8 + u];
                    gv[g] = s;
                }
                float cc = sigm(gv[1]) * c0r[j] + sigm(gv[0]) * tanh_f(gv[2]);
                c0r[j] = cc;
                float h = sigm(gv[3]) * tanh_f(cc);
                store_frag_h((uchar*)g_h0f[t & 1], u0 + u, b, h);
            }
        }
    }
}

// ---------------- out: out[b][t][o] = blin[o] + sum_k h1buf[t][k][b] * WlinT[k][o] ----------------
__global__ __launch_bounds__(256) void out_kernel(const float* __restrict__ blin,
                                                  float* __restrict__ out) {
    int t = blockIdx.y;
    int o0 = blockIdx.x * 64;
    int tid = threadIdx.x;
    int w = tid >> 5, l = tid & 31;

    __shared__ float sh[64 * 64];   // [k][b]
    float acc0[8], acc1[8];
#pragma unroll
    for (int i = 0; i < 8; i++) { acc0[i] = 0.0f; acc1[i] = 0.0f; }

    for (int k0 = 0; k0 < H; k0 += 64) {
        __syncthreads();
#pragma unroll
        for (int r = 0; r < 4; r++) {
            int idx = tid + r * 256;
            ((float4*)sh)[idx] =
                *(((const float4*)&g_h1buf[((size_t)t * H + k0) * B]) + idx);
        }
        __syncthreads();
#pragma unroll 8
        for (int kk = 0; kk < 64; kk++) {
            const float* wr = &g_WlinT[(size_t)(k0 + kk) * DOUT + o0];
            float wa = wr[l];
            float wb = wr[32 + l];
#pragma unroll
            for (int i = 0; i < 8; i++) {
                float av = sh[kk * 64 + w * 8 + i];
                acc0[i] += wa * av;
                acc1[i] += wb * av;
            }
        }
    }
    float ba = blin[o0 + l], bb = blin[o0 + 32 + l];
#pragma unroll
    for (int i = 0; i < 8; i++) {
        int b = w * 8 + i;
        size_t base = ((size_t)b * T + t) * DOUT + o0;
        out[base + l] = acc0[i] + ba;
        out[base + 32 + l] = acc1[i] + bb;
    }
}

// ---------------- launch ----------------
extern "C" void kernel_launch(void* const* d_in, const int* in_sizes, int n_in,
                              void* d_out, int out_size) {
    const float* z    = (const float*)d_in[0];
    const float* x    = (const float*)d_in[1];
    const float* Wih0 = (const float*)d_in[2];
    const float* Whh0 = (const float*)d_in[3];
    const float* bih0 = (const float*)d_in[4];
    const float* bhh0 = (const float*)d_in[5];
    const float* Wih1 = (const float*)d_in[6];
    const float* Whh1 = (const float*)d_in[7];
    const float* bih1 = (const float*)d_in[8];
    const float* bhh1 = (const float*)d_in[9];
    const float* Wlin = (const float*)d_in[10];
    const float* blin = (const float*)d_in[11];
    float* out = (float*)d_out;

    cudaFuncSetAttribute(recur_kernel, cudaFuncAttributeMaxDynamicSharedMemorySize,
                         SMEM_BYTES);
    cudaFuncSetAttribute(xproj_kernel, cudaFuncAttributeMaxDynamicSharedMemorySize,
                         XSMEM_BYTES);

    prep_kernel<<<512, 256>>>(z, x, Wih0, Whh0, bih0, bhh0, Wih1, Whh1, bih1, bhh1, Wlin);
    xproj_kernel<<<dim3(G / 64, T), 256, XSMEM_BYTES>>>();
    recur_kernel<<<NBLK, THR, SMEM_BYTES>>>();
    out_kernel<<<dim3(DOUT / 64, T), 256>>>(blin, out);
}

// round 17
// speedup vs baseline: 2.7800x; 1.3064x over previous
#include <cuda_runtime.h>
#include <cuda_bf16.h>
#include <cuda_fp16.h>
#include <cstdint>

#define B    64
#define T    512
#define DIN  256
#define H    1024
#define G    4096   // 4*H
#define DOUT 256
#define NBLK 128
#define THR  256

typedef unsigned long long ull;
typedef unsigned char uchar;

// ---------------- recur SMEM byte layout: 3 stages x (32KB act + 16KB wt) ----------------
#define S_STAGE  49152
#define S_SG     147456              // 4 slices x 2112 floats = 33792 B
#define S_XP     181248              // 2 slots x 8192 B
#define S_BAR    197632              // 3 stage mbarriers + 1 xp mbarrier
#define SMEM_BYTES 197664

// ---------------- xproj SMEM byte layout (fp16 single-term) ----------------
#define XS_A    0                    // 2 chunks x 16384
#define XS_W    32768                // 2 ngrp x 2 chunks x 8192
#define XS_S    65536                // 2 slices x 4416 floats = 35328 B
#define XS_BAR  100864
#define XSMEM_BYTES 100896

// ---------------- device scratch ----------------
__device__ __align__(128) unsigned short g_Wf0[(size_t)NBLK * 8 * 4096];   // layer0 fp16 frag
__device__ __align__(128) unsigned short g_Wf1[(size_t)NBLK * 16 * 4096];  // layer1
__device__ __align__(128) unsigned short g_WxF[(size_t)64 * 16384];        // xproj weights fp16 frag
__device__ __align__(128) unsigned short g_xf[(size_t)T * 16384];          // x fp16 frag: per t, 2 chunks x 16KB
__device__ float g_WlinT[(size_t)H * DOUT];       // [k][o]
__device__ float g_b0[G];
__device__ float g_b1[G];
__device__ float g_xp[(size_t)T * G * B];         // [t][n][b]
__device__ __align__(128) unsigned short g_h0f[2][65536];   // fp16 acts: 8 x 16KB (= 4 big chunks x 32KB)
__device__ __align__(128) unsigned short g_h1f[2][65536];
__device__ float g_h1buf[(size_t)T * H * B];      // [t][u][b] fp32 for out

__device__ volatile unsigned g_bar_gen;
__device__ unsigned g_bar_cnt;

// ---------------- helpers ----------------
__device__ __forceinline__ float sigm(float x) { return 1.0f / (1.0f + __expf(-x)); }
__device__ __forceinline__ float tanh_f(float x) {
    float e = __expf(-2.0f * fabsf(x));
    float t = (1.0f - e) / (1.0f + e);
    return x >= 0.0f ? t : -t;
}
__device__ __forceinline__ void mbar_init(unsigned mbar, unsigned cnt) {
    asm volatile("mbarrier.init.shared.b64 [%0], %1;" :: "r"(mbar), "r"(cnt) : "memory");
}
__device__ __forceinline__ void mbar_expect_tx(unsigned mbar, unsigned bytes) {
    asm volatile("mbarrier.arrive.expect_tx.shared.b64 _, [%0], %1;" :: "r"(mbar), "r"(bytes) : "memory");
}
__device__ __forceinline__ void mbar_wait(unsigned mbar, unsigned phase) {
    asm volatile(
        "{\n\t"
        ".reg .pred P;\n\t"
        "WAIT_%=:\n\t"
        "mbarrier.try_wait.parity.acquire.cta.shared::cta.b64 P, [%0], %1, 0x989680;\n\t"
        "@P bra.uni DONE_%=;\n\t"
        "bra.uni WAIT_%=;\n\t"
        "DONE_%=:\n\t"
        "}"
        :: "r"(mbar), "r"(phase) : "memory");
}
__device__ __forceinline__ void bulk_cp(unsigned dst, const void* src, unsigned bytes, unsigned mbar) {
    asm volatile(
        "cp.async.bulk.shared::cluster.global.mbarrier::complete_tx::bytes [%0], [%1], %2, [%3];"
        :: "r"(dst), "l"(src), "r"(bytes), "r"(mbar) : "memory");
}
// fp16 mma
__device__ __forceinline__ void hmma16816(float4& d, const uint4& a, unsigned b0, unsigned b1) {
    asm volatile("mma.sync.aligned.m16n8k16.row.col.f32.f16.f16.f32 "
                 "{%0,%1,%2,%3}, {%4,%5,%6,%7}, {%8,%9}, {%0,%1,%2,%3};"
                 : "+f"(d.x), "+f"(d.y), "+f"(d.z), "+f"(d.w)
                 : "r"(a.x), "r"(a.y), "r"(a.z), "r"(a.w), "r"(b0), "r"(b1));
}

// ---- fp16 single-plane frag store (16KB chunks of 128 k-rows) ----
__device__ __forceinline__ void store_frag_h(uchar* basearr, int uGlob, int b, float v) {
    int chunk = uGlob >> 7, kl = uGlob & 127;
    int kt = kl >> 4, kk = kl & 15;
    int mt = b >> 4, mm = b & 15;
    int reg = ((kk & 8) >> 2) | ((mm & 8) >> 3);
    int lane = (mm & 7) * 4 + ((kk & 7) >> 1);
    int half = kk & 1;
    int off = kt * 2048 + mt * 512 + lane * 16 + reg * 4 + half * 2;
    *(__half*)(basearr + (size_t)chunk * 16384 + off) = __float2half_rn(v);
}

// fp16 single-term k16-step (act chunk 16KB, wt chunk 8KB)
__device__ __forceinline__ void mma_kt_h(const uchar* actb, const uchar* wtb,
                                         int kt, int mgroup, int lane, float4 (&c)[2][4]) {
    const uchar* ab = actb + kt * 2048 + lane * 16;
    uint4 a0 = *(const uint4*)(ab + (mgroup * 2 + 0) * 512);
    uint4 a1 = *(const uint4*)(ab + (mgroup * 2 + 1) * 512);
    const uchar* wb = wtb + kt * 1024 + lane * 16;
    uint4 b0 = *(const uint4*)(wb);          // nt0: n8#0 (x,y), n8#1 (z,w)
    uint4 b1 = *(const uint4*)(wb + 512);    // nt1: n8#2, n8#3
    hmma16816(c[0][0], a0, b0.x, b0.y);  hmma16816(c[1][0], a1, b0.x, b0.y);
    hmma16816(c[0][1], a0, b0.z, b0.w);  hmma16816(c[1][1], a1, b0.z, b0.w);
    hmma16816(c[0][2], a0, b1.x, b1.y);  hmma16816(c[1][2], a1, b1.x, b1.y);
    hmma16816(c[0][3], a0, b1.z, b1.w);  hmma16816(c[1][3], a1, b1.z, b1.w);
}

// ---------------- prep ----------------
__global__ void prep_kernel(const float* __restrict__ z, const float* __restrict__ x,
                            const float* __restrict__ Wih0, const float* __restrict__ Whh0,
                            const float* __restrict__ bih0, const float* __restrict__ bhh0,
                            const float* __restrict__ Wih1, const float* __restrict__ Whh1,
                            const float* __restrict__ bih1, const float* __restrict__ bhh1,
                            const float* __restrict__ Wlin) {
    size_t stride = (size_t)gridDim.x * blockDim.x;
    size_t tid = (size_t)blockIdx.x * blockDim.x + threadIdx.x;
    if (tid == 0) { g_bar_gen = 0; g_bar_cnt = 0; }

    // layer0 frag weights (fp16): bits half(1) slotq(2) lane(5) nt(1) kt(3) chunk(3) blk
    for (size_t e = tid; e < (size_t)NBLK * 8 * 4096; e += stride) {
        int half = e & 1;
        int slotq = (e >> 1) & 3;
        int lane = (e >> 3) & 31;
        int nt = (e >> 8) & 1;
        int kt = (e >> 9) & 7;
        int chunk = (e >> 12) & 7;
        size_t blk = e >> 15;
        int n8sel = slotq >> 1, kHi = slotq & 1;
        int nn = lane >> 2, tig = lane & 3;
        int kk = kHi * 8 + tig * 2 + half;
        int k = chunk * 128 + kt * 16 + kk;
        int cc = nt * 16 + n8sel * 8 + nn;
        size_t n = (size_t)(cc >> 3) * H + blk * 8 + (cc & 7);
        __half outv = __float2half_rn(Whh0[n * H + k]);
        g_Wf0[e] = *(unsigned short*)&outv;
    }
    // layer1 frag weights (K = 2048: first h0, then h1)
    for (size_t e = tid; e < (size_t)NBLK * 16 * 4096; e += stride) {
        int half = e & 1;
        int slotq = (e >> 1) & 3;
        int lane = (e >> 3) & 31;
        int nt = (e >> 8) & 1;
        int kt = (e >> 9) & 7;
        int chunk = (e >> 12) & 15;
        size_t blk = e >> 16;
        int n8sel = slotq >> 1, kHi = slotq & 1;
        int nn = lane >> 2, tig = lane & 3;
        int kk = kHi * 8 + tig * 2 + half;
        int k = chunk * 128 + kt * 16 + kk;
        int cc = nt * 16 + n8sel * 8 + nn;
        size_t n = (size_t)(cc >> 3) * H + blk * 8 + (cc & 7);
        float w = (k < H) ? Wih1[n * H + k] : Whh1[n * H + (k - H)];
        __half outv = __float2half_rn(w);
        g_Wf1[e] = *(unsigned short*)&outv;
    }
    // xproj frag weights (fp16): bits half(1) slotq(2) lane(5) nt(1) kt(3) chunk(1) ngrp(1) nb(6)
    for (size_t e = tid; e < (size_t)64 * 16384; e += stride) {
        int half = e & 1;
        int slotq = (e >> 1) & 3;
        int lane = (e >> 3) & 31;
        int nt = (e >> 8) & 1;
        int kt = (e >> 9) & 7;
        int chunk = (e >> 12) & 1;
        int ngrp = (e >> 13) & 1;
        size_t nb = e >> 14;
        int n8sel = slotq >> 1, kHi = slotq & 1;
        int nn = lane >> 2, tig = lane & 3;
        int kk = kHi * 8 + tig * 2 + half;
        int k = chunk * 128 + kt * 16 + kk;
        size_t n = nb * 64 + ngrp * 32 + nt * 16 + n8sel * 8 + nn;
        __half outv = __float2half_rn(Wih0[n * DIN + k]);
        g_WxF[e] = *(unsigned short*)&outv;
    }
    // x fp16 frag pack: i = (b*T + tx)*256 + k  (coalesced x reads)
    for (size_t i = tid; i < (size_t)T * B * DIN; i += stride) {
        int k = i & 255;
        int tx = (i >> 8) & (T - 1);
        int b = i >> 17;
        store_frag_h((uchar*)g_xf + (size_t)tx * 32768, k, b, x[i]);
    }
    for (size_t i = tid; i < (size_t)H * DOUT; i += stride) {
        size_t k = i / DOUT, o = i % DOUT;
        g_WlinT[i] = Wlin[o * H + k];
    }
    for (size_t i = tid; i < G; i += stride) {
        g_b0[i] = bih0[i] + bhh0[i];
        g_b1[i] = bih1[i] + bhh1[i];
    }
    for (size_t i = tid; i < H * B; i += stride) {
        int u = i >> 6, b = i & 63;
        float zv = z[(size_t)b * H + u];
        store_frag_h((uchar*)g_h0f[0], u, b, zv);
        store_frag_h((uchar*)g_h1f[0], u, b, zv);
    }
}

// ---------------- xproj (fp16 single-term): xp[t][n][b] = b0[n] + x[b][t-1] . Wih0^T ----------------
__global__ void __launch_bounds__(256, 1) xproj_kernel() {
    extern __shared__ uchar xs[];
    int t = blockIdx.y;
    int nb = blockIdx.x;             // 64-col group
    int tid = threadIdx.x;

    if (t == 0) {   // zero input step: bias only
        int n_local = tid >> 2, bb = (tid & 3) * 16;
        float bv = g_b0[nb * 64 + n_local];
        float4 v = make_float4(bv, bv, bv, bv);
        float4* dst = (float4*)&g_xp[(size_t)(nb * 64 + n_local) * B + bb];
        dst[0] = v; dst[1] = v; dst[2] = v; dst[3] = v;
        return;
    }

    unsigned sb = (unsigned)__cvta_generic_to_shared(xs);
    unsigned bar = sb + XS_BAR;
    if (tid == 0) {
        mbar_init(bar, 1);
        asm volatile("fence.proxy.async.shared::cta;" ::: "memory");
    }
    __syncthreads();
    if (tid == 0) {
        mbar_expect_tx(bar, 65536u);
        bulk_cp(sb + XS_A, (const uchar*)g_xf + (size_t)(t - 1) * 32768, 32768u, bar);
        bulk_cp(sb + XS_W, (const uchar*)g_WxF + (size_t)nb * 32768, 32768u, bar);
    }
    mbar_wait(bar, 0);

    int wid = tid >> 5, lane = tid & 31;
    int ksx = wid & 1, ngrp = (wid >> 1) & 1, mgrp = wid >> 2;
    float4 cacc[2][4];
#pragma unroll
    for (int i = 0; i < 2; i++)
#pragma unroll
        for (int j = 0; j < 4; j++) cacc[i][j] = make_float4(0.f, 0.f, 0.f, 0.f);

    const uchar* actb = xs + XS_A + ksx * 16384;
    const uchar* wtb  = xs + XS_W + ngrp * 16384 + ksx * 8192;
#pragma unroll
    for (int kt = 0; kt < 8; kt++)
        mma_kt_h(actb, wtb, kt, mgrp, lane, cacc);

    // stage [b][n] per k-slice, stride 69
    float* sgx = (float*)(xs + XS_S) + ksx * 4416;
#pragma unroll
    for (int mt = 0; mt < 2; mt++)
#pragma unroll
        for (int j = 0; j < 4; j++) {
            float4 v = cacc[mt][j];
            int row0 = mgrp * 32 + mt * 16 + (lane >> 2);
            int col = ngrp * 32 + j * 8 + (lane & 3) * 2;
            sgx[row0 * 69 + col] = v.x;
            sgx[row0 * 69 + col + 1] = v.y;
            sgx[(row0 + 8) * 69 + col] = v.z;
            sgx[(row0 + 8) * 69 + col + 1] = v.w;
        }
    __syncthreads();

    const float* sg0 = (const float*)(xs + XS_S);
    const float* sg1 = sg0 + 4416;
    int n_local = tid >> 2, bb = (tid & 3) * 16;
    float bv = g_b0[nb * 64 + n_local];
    float* dst = &g_xp[((size_t)t * G + nb * 64 + n_local) * B + bb];
#pragma unroll
    for (int q = 0; q < 4; q++) {
        float4 v;
        v.x = sg0[(bb + q * 4 + 0) * 69 + n_local] + sg1[(bb + q * 4 + 0) * 69 + n_local] + bv;
        v.y = sg0[(bb + q * 4 + 1) * 69 + n_local] + sg1[(bb + q * 4 + 1) * 69 + n_local] + bv;
        v.z = sg0[(bb + q * 4 + 2) * 69 + n_local] + sg1[(bb + q * 4 + 2) * 69 + n_local] + bv;
        v.w = sg0[(bb + q * 4 + 3) * 69 + n_local] + sg1[(bb + q * 4 + 3) * 69 + n_local] + bv;
        ((float4*)dst)[q] = v;
    }
}

// ---------------- persistent recurrent kernel ----------------
__device__ __forceinline__ void grid_sync(unsigned target) {
    __syncthreads();
    if (threadIdx.x == 0) {
        __threadfence();
        if (atomicAdd(&g_bar_cnt, 1u) == NBLK - 1) {
            g_bar_cnt = 0;
            __threadfence();
            g_bar_gen = target;
        } else {
            while (g_bar_gen < target) {}
            __threadfence();
        }
    }
    __syncthreads();
}

__device__ __forceinline__ void issue_stage(unsigned sb, int stage,
                                            const uchar* act, const uchar* wt) {
    unsigned bar = sb + S_BAR + stage * 8;
    mbar_expect_tx(bar, 49152u);
    bulk_cp(sb + stage * S_STAGE, act, 32768u, bar);
    bulk_cp(sb + stage * S_STAGE + 32768, wt, 16384u, bar);
}

// issue the xp gate slice for step tt into slot
__device__ __forceinline__ void issue_xp(unsigned sb, int slot, int tt, int u0) {
    unsigned bar = sb + S_BAR + 24;
    mbar_expect_tx(bar, 8192u);
#pragma unroll
    for (int g = 0; g < 4; g++)
        bulk_cp(sb + S_XP + slot * 8192 + g * 2048,
                &g_xp[((size_t)tt * G + g * H + u0) * B], 2048u, bar);
}

// chunk sources, CK=256 (12 chunks: 8 L1, 4 L0-next)
__device__ __forceinline__ void chunk_src(int i, const uchar* h0src, const uchar* h1src,
                                          const uchar* wf0base, const uchar* wf1base,
                                          const uchar*& act, const uchar*& wt) {
    if (i < 8) {    // layer1 chunk
        act = (i < 4) ? h0src + (size_t)i * 32768 : h1src + (size_t)(i - 4) * 32768;
        wt = wf1base + (size_t)i * 16384;
    } else {        // layer0 (next step) chunk
        act = h0src + (size_t)(i - 8) * 32768;
        wt = wf0base + (size_t)(i - 8) * 16384;
    }
}

__global__ void __launch_bounds__(THR, 1) recur_kernel() {
    extern __shared__ uchar smem[];
    unsigned sb = (unsigned)__cvta_generic_to_shared(smem);
    float* sg4 = (float*)(smem + S_SG);

    int tid = threadIdx.x;
    int blk = blockIdx.x;
    int wrp = tid >> 5, lane = tid & 31;
    int ks = wrp & 3;          // K-split slice: handles kt = ks, ks+4 per 128-row subchunk
    int mgroup = wrp >> 2;     // batches mgroup*32 .. +31
    int u0 = blk * 8;

    // gate-phase ownership: 2 (unit,batch) items per thread
    int u_[2], b_[2];
    float b1v[2][4];
#pragma unroll
    for (int j = 0; j < 2; j++) {
        int item = tid + j * THR;
        u_[j] = item >> 6;
        b_[j] = item & 63;
#pragma unroll
        for (int g = 0; g < 4; g++)
            b1v[j][g] = g_b1[g * H + u0 + u_[j]];
    }

    if (tid == 0) {
        mbar_init(sb + S_BAR, 1);
        mbar_init(sb + S_BAR + 8, 1);
        mbar_init(sb + S_BAR + 16, 1);
        mbar_init(sb + S_BAR + 24, 1);   // xp barrier
        asm volatile("fence.proxy.async.shared::cta;" ::: "memory");
    }
    __syncthreads();

    unsigned ph_bits = 0;      // per-stage phase parity
    unsigned ph_xp = 0;
    float c0r[2] = {0.0f, 0.0f};
    float c1r[2] = {0.0f, 0.0f};

    const uchar* wf0base = (const uchar*)&g_Wf0[(size_t)blk * 8 * 4096];
    const uchar* wf1base = (const uchar*)&g_Wf1[(size_t)blk * 16 * 4096];

    float4 acc0[2][4], acc1[2][4];

    // ================= prologue: L0(0) (4 chunks of 256 k) =================
    {
        const uchar* h00 = (const uchar*)g_h0f[0];
        if (tid == 0) {
            issue_xp(sb, 0, 0, u0);
            issue_stage(sb, 0, h00, wf0base);
            issue_stage(sb, 1, h00 + 32768, wf0base + 16384);
        }
#pragma unroll
        for (int i = 0; i < 2; i++)
#pragma unroll
            for (int j = 0; j < 4; j++) acc0[i][j] = make_float4(0.f, 0.f, 0.f, 0.f);
        for (int i = 0; i < 4; i++) {
            int stage = i % 3;
            if (tid == 0 && i + 2 < 4)
                issue_stage(sb, (i + 2) % 3, h00 + (size_t)(i + 2) * 32768,
                            wf0base + (size_t)(i + 2) * 16384);
            mbar_wait(sb + S_BAR + stage * 8, (ph_bits >> stage) & 1);
            ph_bits ^= 1u << stage;
            const uchar* actb = smem + stage * S_STAGE;
            const uchar* wtb = actb + 32768;
            mma_kt_h(actb, wtb, ks, mgroup, lane, acc0);
            mma_kt_h(actb, wtb, ks + 4, mgroup, lane, acc0);
            mma_kt_h(actb + 16384, wtb + 8192, ks, mgroup, lane, acc0);
            mma_kt_h(actb + 16384, wtb + 8192, ks + 4, mgroup, lane, acc0);
            __syncthreads();
        }
        // L0(0) gates -> h0f[1]
        float* sgS = sg4 + ks * 2112;
#pragma unroll
        for (int mt = 0; mt < 2; mt++)
#pragma unroll
            for (int j = 0; j < 4; j++) {
                float4 v = acc0[mt][j];
                int row0 = mgroup * 32 + mt * 16 + (lane >> 2);
                int colb = j * 8 + (lane & 3) * 2;
                sgS[row0 * 33 + colb] = v.x;
                sgS[row0 * 33 + colb + 1] = v.y;
                sgS[(row0 + 8) * 33 + colb] = v.z;
                sgS[(row0 + 8) * 33 + colb + 1] = v.w;
            }
        __syncthreads();
        mbar_wait(sb + S_BAR + 24, ph_xp & 1);
        ph_xp ^= 1;
        const float* xpS = (const float*)(smem + S_XP);   // slot 0
#pragma unroll
        for (int j = 0; j < 2; j++) {
            int u = u_[j], b = b_[j];
            float gv[4];
#pragma unroll
            for (int g = 0; g < 4; g++) {
                float s = xpS[g * 512 + u * 64 + b];
#pragma unroll
                for (int sI = 0; sI < 4; sI++)
                    s += sg4[sI * 2112 + b * 33 + g * 8 + u];
                gv[g] = s;
            }
            float cc = sigm(gv[1]) * c0r[j] + sigm(gv[0]) * tanh_f(gv[2]);
            c0r[j] = cc;
            float h = sigm(gv[3]) * tanh_f(cc);
            store_frag_h((uchar*)g_h0f[1], u0 + u, b, h);
        }
    }

    // ================= main loop: one grid sync per step =================
    for (int t = 0; t < T; t++) {
        grid_sync(t + 1);
        const uchar* h0src = (const uchar*)g_h0f[(t + 1) & 1];  // h0(t)
        const uchar* h1src = (const uchar*)g_h1f[t & 1];        // h1(t-1)
        int NCH = (t == T - 1) ? 8 : 12;

        if (tid == 0) {
            if (t + 1 < T) issue_xp(sb, (t + 1) & 1, t + 1, u0);
            const uchar *a0, *w0, *a1, *w1;
            chunk_src(0, h0src, h1src, wf0base, wf1base, a0, w0);
            chunk_src(1, h0src, h1src, wf0base, wf1base, a1, w1);
            issue_stage(sb, 0, a0, w0);
            issue_stage(sb, 1, a1, w1);
        }
#pragma unroll
        for (int i = 0; i < 2; i++)
#pragma unroll
            for (int j = 0; j < 4; j++) {
                acc1[i][j] = make_float4(0.f, 0.f, 0.f, 0.f);
                acc0[i][j] = make_float4(0.f, 0.f, 0.f, 0.f);
            }

        for (int i = 0; i < NCH; i++) {
            int stage = i % 3;
            if (tid == 0 && i + 2 < NCH) {
                const uchar *an, *wn;
                chunk_src(i + 2, h0src, h1src, wf0base, wf1base, an, wn);
                issue_stage(sb, (i + 2) % 3, an, wn);
            }
            mbar_wait(sb + S_BAR + stage * 8, (ph_bits >> stage) & 1);
            ph_bits ^= 1u << stage;
            const uchar* actb = smem + stage * S_STAGE;
            const uchar* wtb = actb + 32768;
            if (i < 8) {
                mma_kt_h(actb, wtb, ks, mgroup, lane, acc1);
                mma_kt_h(actb, wtb, ks + 4, mgroup, lane, acc1);
                mma_kt_h(actb + 16384, wtb + 8192, ks, mgroup, lane, acc1);
                mma_kt_h(actb + 16384, wtb + 8192, ks + 4, mgroup, lane, acc1);
            } else {
                mma_kt_h(actb, wtb, ks, mgroup, lane, acc0);
                mma_kt_h(actb, wtb, ks + 4, mgroup, lane, acc0);
                mma_kt_h(actb + 16384, wtb + 8192, ks, mgroup, lane, acc0);
                mma_kt_h(actb + 16384, wtb + 8192, ks + 4, mgroup, lane, acc0);
            }
            __syncthreads();

            if (i == 7) {
                // ---- L1(t) gates interleaved: TMA for L0 chunks continues ----
                {
                    float* sgS = sg4 + ks * 2112;
#pragma unroll
                    for (int mt = 0; mt < 2; mt++)
#pragma unroll
                        for (int j = 0; j < 4; j++) {
                            float4 v = acc1[mt][j];
                            int row0 = mgroup * 32 + mt * 16 + (lane >> 2);
                            int colb = j * 8 + (lane & 3) * 2;
                            sgS[row0 * 33 + colb] = v.x;
                            sgS[row0 * 33 + colb + 1] = v.y;
                            sgS[(row0 + 8) * 33 + colb] = v.z;
                            sgS[(row0 + 8) * 33 + colb + 1] = v.w;
                        }
                }
                __syncthreads();
#pragma unroll
                for (int j = 0; j < 2; j++) {
                    int u = u_[j], b = b_[j];
                    float gv[4];
#pragma unroll
                    for (int g = 0; g < 4; g++) {
                        float s = b1v[j][g];
#pragma unroll
                        for (int sI = 0; sI < 4; sI++)
                            s += sg4[sI * 2112 + b * 33 + g * 8 + u];
                        gv[g] = s;
                    }
                    float cc = sigm(gv[1]) * c1r[j] + sigm(gv[0]) * tanh_f(gv[2]);
                    c1r[j] = cc;
                    float h = sigm(gv[3]) * tanh_f(cc);
                    store_frag_h((uchar*)g_h1f[(t + 1) & 1], u0 + u, b, h);
                    g_h1buf[(size_t)t * H * B + (u0 + u) * B + b] = h;
                }
                __syncthreads();   // protect sg4 before L0 gate staging reuses it
            }
        }

        // ---- L0(t+1) gates -> h0f[t&1] ----
        if (t + 1 < T) {
            {
                float* sgS = sg4 + ks * 2112;
#pragma unroll
                for (int mt = 0; mt < 2; mt++)
#pragma unroll
                    for (int j = 0; j < 4; j++) {
                        float4 v = acc0[mt][j];
                        int row0 = mgroup * 32 + mt * 16 + (lane >> 2);
                        int colb = j * 8 + (lane & 3) * 2;
                        sgS[row0 * 33 + colb] = v.x;
                        sgS[row0 * 33 + colb + 1] = v.y;
                        sgS[(row0 + 8) * 33 + colb] = v.z;
                        sgS[(row0 + 8) * 33 + colb + 1] = v.w;
                    }
            }
            __syncthreads();
            mbar_wait(sb + S_BAR + 24, ph_xp & 1);
            ph_xp ^= 1;
            const float* xpS = (const float*)(smem + S_XP + ((t + 1) & 1) * 8192);
#pragma unroll
            for (int j = 0; j < 2; j++) {
                int u = u_[j], b = b_[j];
                float gv[4];
#pragma unroll
                for (int g = 0; g < 4; g++) {
                    float s = xpS[g * 512 + u * 64 + b];
#pragma unroll
                    for (int sI = 0; sI < 4; sI++)
                        s += sg4[sI * 2112 + b * 33 + g * 8 + u];
                    gv[g] = s;
                }
                float cc = sigm(gv[1]) * c0r[j] + sigm(gv[0]) * tanh_f(gv[2]);
                c0r[j] = cc;
                float h = sigm(gv[3]) * tanh_f(cc);
                store_frag_h((uchar*)g_h0f[t & 1], u0 + u, b, h);
            }
        }
    }
}

// ---------------- out: out[b][t][o] = blin[o] + sum_k h1buf[t][k][b] * WlinT[k][o] ----------------
__global__ __launch_bounds__(256) void out_kernel(const float* __restrict__ blin,
                                                  float* __restrict__ out) {
    int t = blockIdx.y;
    int o0 = blockIdx.x * 64;
    int tid = threadIdx.x;
    int w = tid >> 5, l = tid & 31;

    __shared__ float sh[64 * 64];   // [k][b]
    float acc0[8], acc1[8];
#pragma unroll
    for (int i = 0; i < 8; i++) { acc0[i] = 0.0f; acc1[i] = 0.0f; }

    for (int k0 = 0; k0 < H; k0 += 64) {
        __syncthreads();
#pragma unroll
        for (int r = 0; r < 4; r++) {
            int idx = tid + r * 256;
            ((float4*)sh)[idx] =
                *(((const float4*)&g_h1buf[((size_t)t * H + k0) * B]) + idx);
        }
        __syncthreads();
#pragma unroll 8
        for (int kk = 0; kk < 64; kk++) {
            const float* wr = &g_WlinT[(size_t)(k0 + kk) * DOUT + o0];
            float wa = wr[l];
            float wb = wr[32 + l];
#pragma unroll
            for (int i = 0; i < 8; i++) {
                float av = sh[kk * 64 + w * 8 + i];
                acc0[i] += wa * av;
                acc1[i] += wb * av;
            }
        }
    }
    float ba = blin[o0 + l], bb = blin[o0 + 32 + l];
#pragma unroll
    for (int i = 0; i < 8; i++) {
        int b = w * 8 + i;
        size_t base = ((size_t)b * T + t) * DOUT + o0;
        out[base + l] = acc0[i] + ba;
        out[base + 32 + l] = acc1[i] + bb;
    }
}

// ---------------- launch ----------------
extern "C" void kernel_launch(void* const* d_in, const int* in_sizes, int n_in,
                              void* d_out, int out_size) {
    const float* z    = (const float*)d_in[0];
    const float* x    = (const float*)d_in[1];
    const float* Wih0 = (const float*)d_in[2];
    const float* Whh0 = (const float*)d_in[3];
    const float* bih0 = (const float*)d_in[4];
    const float* bhh0 = (const float*)d_in[5];
    const float* Wih1 = (const float*)d_in[6];
    const float* Whh1 = (const float*)d_in[7];
    const float* bih1 = (const float*)d_in[8];
    const float* bhh1 = (const float*)d_in[9];
    const float* Wlin = (const float*)d_in[10];
    const float* blin = (const float*)d_in[11];
    float* out = (float*)d_out;

    cudaFuncSetAttribute(recur_kernel, cudaFuncAttributeMaxDynamicSharedMemorySize,
                         SMEM_BYTES);
    cudaFuncSetAttribute(xproj_kernel, cudaFuncAttributeMaxDynamicSharedMemorySize,
                         XSMEM_BYTES);

    prep_kernel<<<512, 256>>>(z, x, Wih0, Whh0, bih0, bhh0, Wih1, Whh1, bih1, bhh1, Wlin);
    xproj_kernel<<<dim3(G / 64, T), 256, XSMEM_BYTES>>>();
    recur_kernel<<<NBLK, THR, SMEM_BYTES>>>();
    out_kernel<<<dim3(DOUT / 64, T), 256>>>(blin, out);
}